// round 2
// baseline (speedup 1.0000x reference)
#include <cuda_runtime.h>
#include <math.h>

// ---------------- persistent device scratch (no allocations allowed) ----------------
__device__ float  g_buf0[16u*16u*64u*64u*64u];   // conv00 out (raw)   268MB
__device__ float  g_buf1[16u*32u*32u*32u*32u];   // conv0  out (raw)    67MB
__device__ float  g_buf2[16u*64u*16u*16u*16u];   // conv1  out (raw)  16.8MB
__device__ float  g_buf3[16u*64u*8u*8u*8u];      // conv2  out (raw)   2.1MB
__device__ float  g_buf4[16u*64u*4u*4u*4u];      // conv3  out (raw)  0.26MB
__device__ double g_stats[480];                  // per-stage [sum|sumsq]
__device__ float  g_scale[5*64];                 // BN apply: a = g*rsqrt(var+eps)
__device__ float  g_shift[5*64];                 //           b = be - mean*a
__device__ float  g_theta[16*12];                // theta[:, :3, :]

// ---------------- utility kernels ----------------
__global__ void zero_stats_kernel(double* s) {
    int i = threadIdx.x;
    if (i < 480) s[i] = 0.0;
}

__global__ void finalize_kernel(const double* __restrict__ stats,
                                const float* __restrict__ g, const float* __restrict__ be,
                                float* __restrict__ sc, float* __restrict__ sh,
                                int C, double invN) {
    int c = threadIdx.x;
    if (c < C) {
        double mean = stats[c] * invN;
        double var  = stats[C + c] * invN - mean * mean;
        float a = g[c] * (float)(1.0 / sqrt(var + 1e-5));
        sc[c] = a;
        sh[c] = be[c] - (float)mean * a;
    }
}

// ---------------- conv00: 1->16 ch, stride 1, pad 1, 64^3 ----------------
// tile 8^3, 128 threads, each thread: 4 voxels along x, all 16 oc.
__global__ void __launch_bounds__(128) conv00_kernel(
    const float* __restrict__ x, const float* __restrict__ w,
    const float* __restrict__ bias, float* __restrict__ out,
    double* __restrict__ stats) {
    __shared__ float sIn[1000];   // 10^3
    __shared__ float sW[432];     // 16*27
    __shared__ float bsum[16], bsq[16];

    int tid = threadIdx.x;
    int b = blockIdx.y;
    int t = blockIdx.x;
    int tz = t >> 6, ty = (t >> 3) & 7, tx = t & 7;

    if (tid < 16) { bsum[tid] = 0.f; bsq[tid] = 0.f; }

    for (int i = tid; i < 1000; i += 128) {
        int iz = i / 100, iy = (i / 10) % 10, ix = i % 10;
        int gz = tz * 8 - 1 + iz, gy = ty * 8 - 1 + iy, gx = tx * 8 - 1 + ix;
        float v = 0.f;
        if ((unsigned)gz < 64u && (unsigned)gy < 64u && (unsigned)gx < 64u)
            v = x[((b * 64 + gz) * 64 + gy) * 64 + gx];
        sIn[i] = v;
    }
    for (int i = tid; i < 432; i += 128) sW[i] = w[i];
    __syncthreads();

    int sz = tid >> 4, sy = (tid >> 1) & 7, sx = tid & 1;
    float iv[54];
#pragma unroll
    for (int kd = 0; kd < 3; kd++)
#pragma unroll
        for (int kh = 0; kh < 3; kh++) {
            int base = (sz + kd) * 100 + (sy + kh) * 10 + sx * 4;
#pragma unroll
            for (int u = 0; u < 6; u++) iv[(kd * 3 + kh) * 6 + u] = sIn[base + u];
        }

    int gz = tz * 8 + sz, gy = ty * 8 + sy, gx = tx * 8 + sx * 4;
#pragma unroll 1
    for (int oc = 0; oc < 16; oc++) {
        float a0 = 0.f, a1 = 0.f, a2 = 0.f, a3 = 0.f;
#pragma unroll
        for (int kd = 0; kd < 3; kd++)
#pragma unroll
            for (int kh = 0; kh < 3; kh++)
#pragma unroll
                for (int kw = 0; kw < 3; kw++) {
                    float wv = sW[oc * 27 + (kd * 3 + kh) * 3 + kw];
                    int r = (kd * 3 + kh) * 6 + kw;
                    a0 = fmaf(iv[r], wv, a0);
                    a1 = fmaf(iv[r + 1], wv, a1);
                    a2 = fmaf(iv[r + 2], wv, a2);
                    a3 = fmaf(iv[r + 3], wv, a3);
                }
        float bb = bias[oc];
        a0 += bb; a1 += bb; a2 += bb; a3 += bb;
        float4 o = make_float4(a0, a1, a2, a3);
        *reinterpret_cast<float4*>(&out[(((b * 16 + oc) * 64 + gz) * 64 + gy) * 64 + gx]) = o;

        float s = a0 + a1 + a2 + a3;
        float q = a0 * a0 + a1 * a1 + a2 * a2 + a3 * a3;
#pragma unroll
        for (int off = 16; off > 0; off >>= 1) {
            s += __shfl_down_sync(0xffffffffu, s, off);
            q += __shfl_down_sync(0xffffffffu, q, off);
        }
        if ((tid & 31) == 0) { atomicAdd(&bsum[oc], s); atomicAdd(&bsq[oc], q); }
    }
    __syncthreads();
    if (tid < 16) {
        atomicAdd(&stats[tid], (double)bsum[tid]);
        atomicAdd(&stats[16 + tid], (double)bsq[tid]);
    }
}

// ---------------- generic stride-2 conv: CIN -> COUTB (per z-block), pad 1 ----------------
// out tile 4^3 (in tile 9^3 per ic). 128 threads = 32 voxel-pairs x (COUTB/OCPT) groups.
// Applies BN scale/shift + relu of the PREVIOUS stage while loading input to smem.
template <int CIN, int COUTB, int OCPT>
__global__ void __launch_bounds__(128) conv_s2_kernel(
    const float* __restrict__ in, const float* __restrict__ w,
    const float* __restrict__ bias,
    const float* __restrict__ tsc, const float* __restrict__ tsh,
    float* __restrict__ out, double* __restrict__ stats,
    int Din, int Dout, int ntile, int coutTot) {
    constexpr int ICC = 16;
    constexpr int NIN = ICC * 729;
    constexpr int NW  = COUTB * ICC * 27;
    extern __shared__ float sm[];
    float* sIn = sm;        // ICC*9*9*9
    float* sW  = sm + NIN;  // COUTB*ICC*27
    __shared__ float bsum[COUTB], bsq[COUTB];

    int tid = threadIdx.x;
    int b = blockIdx.y;
    int ocBase = blockIdx.z * COUTB;
    int t = blockIdx.x;
    int tz = t / (ntile * ntile), ty = (t / ntile) % ntile, tx = t % ntile;
    int pair = tid & 31, group = tid >> 5;
    int oz = pair >> 3, oy = (pair >> 1) & 3, px = pair & 1;

    if (tid < COUTB) { bsum[tid] = 0.f; bsq[tid] = 0.f; }

    float acc0[OCPT], acc1[OCPT];
#pragma unroll
    for (int j = 0; j < OCPT; j++) { acc0[j] = 0.f; acc1[j] = 0.f; }

    for (int c0 = 0; c0 < CIN; c0 += ICC) {
        __syncthreads();
        for (int i = tid; i < NIN; i += 128) {
            int ic = i / 729, r = i % 729;
            int iz = r / 81, iy = (r / 9) % 9, ix = r % 9;
            int gz = tz * 8 - 1 + iz, gy = ty * 8 - 1 + iy, gx = tx * 8 - 1 + ix;
            float v = 0.f;
            if ((unsigned)gz < (unsigned)Din && (unsigned)gy < (unsigned)Din &&
                (unsigned)gx < (unsigned)Din) {
                v = in[(((b * CIN + c0 + ic) * Din + gz) * Din + gy) * Din + gx];
                v = fmaxf(fmaf(v, tsc[c0 + ic], tsh[c0 + ic]), 0.f);
            }
            sIn[i] = v;
        }
        for (int i = tid; i < NW; i += 128) {
            int ocl = i / (ICC * 27), r = i % (ICC * 27);
            sW[i] = w[((ocBase + ocl) * CIN + c0) * 27 + r];
        }
        __syncthreads();

#pragma unroll 1
        for (int ic = 0; ic < ICC; ic++) {
            const float* wrow = &sW[(group * OCPT) * ICC * 27 + ic * 27];
#pragma unroll
            for (int kd = 0; kd < 3; kd++)
#pragma unroll
                for (int kh = 0; kh < 3; kh++) {
                    int base = ((ic * 9 + (2 * oz + kd)) * 9 + (2 * oy + kh)) * 9 + 4 * px;
                    float ivs[5];
#pragma unroll
                    for (int u = 0; u < 5; u++) ivs[u] = sIn[base + u];
#pragma unroll
                    for (int kw = 0; kw < 3; kw++) {
#pragma unroll
                        for (int j = 0; j < OCPT; j++) {
                            float wv = wrow[j * ICC * 27 + (kd * 3 + kh) * 3 + kw];
                            acc0[j] = fmaf(ivs[kw], wv, acc0[j]);
                            acc1[j] = fmaf(ivs[kw + 2], wv, acc1[j]);
                        }
                    }
                }
        }
    }

    int gz = tz * 4 + oz, gy = ty * 4 + oy, gx = tx * 4 + 2 * px;
#pragma unroll
    for (int j = 0; j < OCPT; j++) {
        int oc = ocBase + group * OCPT + j;
        float bb = bias[oc];
        float o0 = acc0[j] + bb, o1 = acc1[j] + bb;
        float2 o2 = make_float2(o0, o1);
        *reinterpret_cast<float2*>(
            &out[(((b * coutTot + oc) * Dout + gz) * Dout + gy) * Dout + gx]) = o2;

        float s = o0 + o1, q = o0 * o0 + o1 * o1;
#pragma unroll
        for (int off = 16; off > 0; off >>= 1) {
            s += __shfl_down_sync(0xffffffffu, s, off);
            q += __shfl_down_sync(0xffffffffu, q, off);
        }
        if (pair == 0) {
            atomicAdd(&bsum[group * OCPT + j], s);
            atomicAdd(&bsq[group * OCPT + j], q);
        }
    }
    __syncthreads();
    if (tid < COUTB) {
        atomicAdd(&stats[ocBase + tid], (double)bsum[tid]);
        atomicAdd(&stats[coutTot + ocBase + tid], (double)bsq[tid]);
    }
}

// ---------------- heads: 12 dot products + affine matrix composition ----------------
__device__ __forceinline__ void ident4(float* M) {
#pragma unroll
    for (int i = 0; i < 16; i++) M[i] = (i % 5 == 0) ? 1.f : 0.f;
}
__device__ __forceinline__ void mm4(const float* A, const float* B, float* C) {
#pragma unroll
    for (int i = 0; i < 4; i++)
#pragma unroll
        for (int j = 0; j < 4; j++)
            C[i * 4 + j] = A[i * 4 + 0] * B[0 + j] + A[i * 4 + 1] * B[4 + j] +
                           A[i * 4 + 2] * B[8 + j] + A[i * 4 + 3] * B[12 + j];
}

__global__ void __launch_bounds__(256) heads_kernel(
    const float* __restrict__ xs, const float* __restrict__ sc, const float* __restrict__ sh,
    const float* __restrict__ tw, const float* __restrict__ tb,
    const float* __restrict__ rw, const float* __restrict__ rb,
    const float* __restrict__ sw_, const float* __restrict__ sb_,
    const float* __restrict__ shw, const float* __restrict__ shb,
    float* __restrict__ theta) {
    __shared__ float red[12 * 256];
    int b = blockIdx.x, tid = threadIdx.x;
    float p[12];
#pragma unroll
    for (int r = 0; r < 12; r++) p[r] = 0.f;
    for (int i = tid; i < 4096; i += 256) {
        int c = i >> 6;
        float v = fmaxf(fmaf(xs[b * 4096 + i], sc[c], sh[c]), 0.f);
#pragma unroll
        for (int r = 0; r < 3; r++) {
            p[r]     = fmaf(v, tw[r * 4096 + i], p[r]);
            p[3 + r] = fmaf(v, rw[r * 4096 + i], p[3 + r]);
            p[6 + r] = fmaf(v, sw_[r * 4096 + i], p[6 + r]);
            p[9 + r] = fmaf(v, shw[r * 4096 + i], p[9 + r]);
        }
    }
#pragma unroll
    for (int r = 0; r < 12; r++) red[r * 256 + tid] = p[r];
    __syncthreads();
    for (int s = 128; s > 0; s >>= 1) {
        if (tid < s)
#pragma unroll
            for (int r = 0; r < 12; r++) red[r * 256 + tid] += red[r * 256 + tid + s];
        __syncthreads();
    }
    if (tid == 0) {
        const float PI4 = 0.7853981633974483f;
        float tr[3], ro[3], scp[3], shp[3];
#pragma unroll
        for (int r = 0; r < 3; r++) {
            tr[r]  = tanhf(red[r * 256] + tb[r]) * 0.1f;
            ro[r]  = tanhf(red[(3 + r) * 256] + rb[r]) * PI4;
            scp[r] = tanhf(red[(6 + r) * 256] + sb_[r]) * 0.2f;
            shp[r] = tanhf(red[(9 + r) * 256] + shb[r]) * PI4;
        }
        float c0 = cosf(ro[0]), s0 = sinf(ro[0]);
        float c1 = cosf(ro[1]), s1 = sinf(ro[1]);
        float c2 = cosf(ro[2]), s2 = sinf(ro[2]);
        float cs0 = cosf(shp[0]), ss0 = sinf(shp[0]);
        float cs1 = cosf(shp[1]), ss1 = sinf(shp[1]);
        float cs2 = cosf(shp[2]), ss2 = sinf(shp[2]);

        float T[16], R1[16], R2[16], R3[16], S[16], H1[16], H2[16], H3[16];
        float R[16], Sh[16], ShT[16], A[16], B[16];
        ident4(T);  T[3] = tr[0]; T[7] = tr[1]; T[11] = tr[2];
        ident4(R1); R1[0] = c0; R1[1] = -s0; R1[4] = s0; R1[5] = c0;
        ident4(R2); R2[5] = c1; R2[6] = -s1; R2[9] = s1; R2[10] = c1;
        ident4(R3); R3[0] = c2; R3[1] = -s2; R3[4] = s2; R3[5] = c2;
        ident4(S);  S[0] = expf(scp[0]); S[5] = expf(scp[1]); S[10] = expf(scp[2]);
        ident4(H1); H1[5] = cs0; H1[6] = -ss0; H1[9] = ss0; H1[10] = cs0;
        ident4(H2); H2[0] = cs1; H2[2] = ss1; H2[8] = -ss1; H2[10] = cs1;
        ident4(H3); H3[0] = cs2; H3[1] = -ss2; H3[4] = ss2; H3[5] = cs2;

        mm4(R1, R2, A); mm4(A, R3, R);
        mm4(H1, H2, A); mm4(A, H3, Sh);
#pragma unroll
        for (int i = 0; i < 4; i++)
#pragma unroll
            for (int j = 0; j < 4; j++) ShT[i * 4 + j] = Sh[j * 4 + i];
        mm4(Sh, S, A); mm4(A, ShT, B); mm4(B, R, A); mm4(A, T, B);
#pragma unroll
        for (int i = 0; i < 12; i++) theta[b * 12 + i] = B[i];
    }
}

// ---------------- trilinear grid sample (zero padding, clamped gather) ----------------
__global__ void __launch_bounds__(256) sampler_kernel(
    const float* __restrict__ x, const float* __restrict__ theta,
    float* __restrict__ out) {
    int idx = blockIdx.x * 256 + threadIdx.x;
    int b = idx >> 18;
    int r = idx & 262143;
    int z = r >> 12, y = (r >> 6) & 63, xq = r & 63;
    const float st = 2.f / 63.f;
    float xx = fmaf((float)xq, st, -1.f);
    float yy = fmaf((float)y, st, -1.f);
    float zz = fmaf((float)z, st, -1.f);
    const float* th = &theta[b * 12];
    float g0 = th[0] * xx + th[1] * yy + th[2] * zz + th[3];
    float g1 = th[4] * xx + th[5] * yy + th[6] * zz + th[7];
    float g2 = th[8] * xx + th[9] * yy + th[10] * zz + th[11];
    float fx = ((g0 + 1.f) * 64.f - 1.f) * 0.5f;
    float fy = ((g1 + 1.f) * 64.f - 1.f) * 0.5f;
    float fz = ((g2 + 1.f) * 64.f - 1.f) * 0.5f;
    float x0f = floorf(fx), y0f = floorf(fy), z0f = floorf(fz);
    int x0 = (int)x0f, y0 = (int)y0f, z0 = (int)z0f;
    float wx1 = fx - x0f, wx0 = 1.f - wx1;
    float wy1 = fy - y0f, wy0 = 1.f - wy1;
    float wz1 = fz - z0f, wz0 = 1.f - wz1;
    const float* xb = &x[b << 18];
    float acc = 0.f;
#pragma unroll
    for (int dz = 0; dz < 2; dz++) {
        int zc = z0 + dz;
        float wz = dz ? wz1 : wz0;
        bool vz = (zc >= 0 && zc < 64);
        int zi = min(max(zc, 0), 63);
#pragma unroll
        for (int dy = 0; dy < 2; dy++) {
            int yc = y0 + dy;
            float wy = dy ? wy1 : wy0;
            bool vy = vz && (yc >= 0 && yc < 64);
            int yi = min(max(yc, 0), 63);
#pragma unroll
            for (int dx = 0; dx < 2; dx++) {
                int xc = x0 + dx;
                float wgt = wz * wy * (dx ? wx1 : wx0);
                bool v = vy && (xc >= 0 && xc < 64);
                int xi = min(max(xc, 0), 63);
                float val = xb[(zi * 64 + yi) * 64 + xi];
                acc += v ? val * wgt : 0.f;
            }
        }
    }
    out[idx] = acc;
}

// ---------------- launch ----------------
extern "C" void kernel_launch(void* const* d_in, const int* in_sizes, int n_in,
                              void* d_out, int out_size) {
    const float* x    = (const float*)d_in[0];
    const float* w00  = (const float*)d_in[1];
    const float* b00  = (const float*)d_in[2];
    const float* g00  = (const float*)d_in[3];
    const float* be00 = (const float*)d_in[4];
    const float* w0   = (const float*)d_in[5];
    const float* b0   = (const float*)d_in[6];
    const float* g0   = (const float*)d_in[7];
    const float* be0  = (const float*)d_in[8];
    const float* w1   = (const float*)d_in[9];
    const float* b1   = (const float*)d_in[10];
    const float* g1   = (const float*)d_in[11];
    const float* be1  = (const float*)d_in[12];
    const float* w2   = (const float*)d_in[13];
    const float* b2   = (const float*)d_in[14];
    const float* g2   = (const float*)d_in[15];
    const float* be2  = (const float*)d_in[16];
    const float* w3   = (const float*)d_in[17];
    const float* b3   = (const float*)d_in[18];
    const float* g3   = (const float*)d_in[19];
    const float* be3  = (const float*)d_in[20];
    const float* tw   = (const float*)d_in[21];
    const float* tb   = (const float*)d_in[22];
    const float* rw   = (const float*)d_in[23];
    const float* rb   = (const float*)d_in[24];
    const float* sw   = (const float*)d_in[25];
    const float* sb   = (const float*)d_in[26];
    const float* shw  = (const float*)d_in[27];
    const float* shb  = (const float*)d_in[28];

    float *buf0, *buf1, *buf2, *buf3, *buf4, *scale, *shift, *theta;
    double* stats;
    cudaGetSymbolAddress((void**)&buf0, g_buf0);
    cudaGetSymbolAddress((void**)&buf1, g_buf1);
    cudaGetSymbolAddress((void**)&buf2, g_buf2);
    cudaGetSymbolAddress((void**)&buf3, g_buf3);
    cudaGetSymbolAddress((void**)&buf4, g_buf4);
    cudaGetSymbolAddress((void**)&stats, g_stats);
    cudaGetSymbolAddress((void**)&scale, g_scale);
    cudaGetSymbolAddress((void**)&shift, g_shift);
    cudaGetSymbolAddress((void**)&theta, g_theta);

    const int SM_L0 = (16 * 729 + 32 * 16 * 27) * 4;  // 101,952 B
    const int SM_L12 = (16 * 729 + 64 * 16 * 27) * 4; // 157,248 B
    const int SM_L3 = (16 * 729 + 16 * 16 * 27) * 4;  //  74,304 B
    cudaFuncSetAttribute(conv_s2_kernel<16, 32, 8>,
                         cudaFuncAttributeMaxDynamicSharedMemorySize, SM_L0);
    cudaFuncSetAttribute(conv_s2_kernel<32, 64, 16>,
                         cudaFuncAttributeMaxDynamicSharedMemorySize, SM_L12);
    cudaFuncSetAttribute(conv_s2_kernel<64, 64, 16>,
                         cudaFuncAttributeMaxDynamicSharedMemorySize, SM_L12);
    cudaFuncSetAttribute(conv_s2_kernel<64, 16, 4>,
                         cudaFuncAttributeMaxDynamicSharedMemorySize, SM_L3);

    zero_stats_kernel<<<1, 512>>>(stats);

    // stage 0: conv00 1->16, 64^3
    conv00_kernel<<<dim3(512, 16), 128>>>(x, w00, b00, buf0, stats + 0);
    finalize_kernel<<<1, 64>>>(stats + 0, g00, be00, scale + 0, shift + 0, 16,
                               1.0 / 4194304.0);

    // stage 1: 16->32, 64^3 -> 32^3
    conv_s2_kernel<16, 32, 8><<<dim3(512, 16, 1), 128, SM_L0>>>(
        buf0, w0, b0, scale + 0, shift + 0, buf1, stats + 32, 64, 32, 8, 32);
    finalize_kernel<<<1, 64>>>(stats + 32, g0, be0, scale + 64, shift + 64, 32,
                               1.0 / 524288.0);

    // stage 2: 32->64, 32^3 -> 16^3
    conv_s2_kernel<32, 64, 16><<<dim3(64, 16, 1), 128, SM_L12>>>(
        buf1, w1, b1, scale + 64, shift + 64, buf2, stats + 96, 32, 16, 4, 64);
    finalize_kernel<<<1, 64>>>(stats + 96, g1, be1, scale + 128, shift + 128, 64,
                               1.0 / 65536.0);

    // stage 3: 64->64, 16^3 -> 8^3
    conv_s2_kernel<64, 64, 16><<<dim3(8, 16, 1), 128, SM_L12>>>(
        buf2, w2, b2, scale + 128, shift + 128, buf3, stats + 224, 16, 8, 2, 64);
    finalize_kernel<<<1, 64>>>(stats + 224, g2, be2, scale + 192, shift + 192, 64,
                               1.0 / 8192.0);

    // stage 4: 64->64, 8^3 -> 4^3 (oc split into 4 z-blocks for parallelism)
    conv_s2_kernel<64, 16, 4><<<dim3(1, 16, 4), 128, SM_L3>>>(
        buf3, w3, b3, scale + 192, shift + 192, buf4, stats + 352, 8, 4, 1, 64);
    finalize_kernel<<<1, 64>>>(stats + 352, g3, be3, scale + 256, shift + 256, 64,
                               1.0 / 1024.0);

    // heads + affine composition
    heads_kernel<<<16, 256>>>(buf4, scale + 256, shift + 256, tw, tb, rw, rb, sw, sb,
                              shw, shb, theta);

    // grid sample
    sampler_kernel<<<16384, 256>>>(x, theta, (float*)d_out);
}

// round 4
// speedup vs baseline: 1.1909x; 1.1909x over previous
#include <cuda_runtime.h>
#include <math.h>

// ---------------- persistent device scratch (no allocations allowed) ----------------
__device__ float  g_buf0[16u*16u*64u*64u*64u];   // conv00 out (raw)   268MB
__device__ float  g_buf1[16u*32u*32u*32u*32u];   // conv0  out (raw)    67MB
__device__ float  g_buf2[16u*64u*16u*16u*16u];   // conv1  out (raw)  16.8MB
__device__ float  g_buf3[16u*64u*8u*8u*8u];      // conv2  out (raw)   2.1MB
__device__ float  g_buf4[16u*64u*4u*4u*4u];      // conv3  out (raw)  0.26MB
__device__ double g_stats[480];                  // per-stage [sum|sumsq]
__device__ float  g_scale[5*64];                 // BN apply: a = g*rsqrt(var+eps)
__device__ float  g_shift[5*64];                 //           b = be - mean*a
__device__ float  g_theta[16*12];                // theta[:, :3, :]

// ---------------- utility kernels ----------------
__global__ void zero_stats_kernel(double* s) {
    int i = threadIdx.x;
    if (i < 480) s[i] = 0.0;
}

__global__ void finalize_kernel(const double* __restrict__ stats,
                                const float* __restrict__ g, const float* __restrict__ be,
                                float* __restrict__ sc, float* __restrict__ sh,
                                int C, double invN) {
    int c = threadIdx.x;
    if (c < C) {
        double mean = stats[c] * invN;
        double var  = stats[C + c] * invN - mean * mean;
        float a = g[c] * (float)(1.0 / sqrt(var + 1e-5));
        sc[c] = a;
        sh[c] = be[c] - (float)mean * a;
    }
}

// ---------------- conv00: 1->16 ch, stride 1, pad 1, 64^3 ----------------
__global__ void __launch_bounds__(128) conv00_kernel(
    const float* __restrict__ x, const float* __restrict__ w,
    const float* __restrict__ bias, float* __restrict__ out,
    double* __restrict__ stats) {
    __shared__ float sIn[1000];   // 10^3
    __shared__ float sW[432];     // 16*27
    __shared__ float bsum[16], bsq[16];

    int tid = threadIdx.x;
    int b = blockIdx.y;
    int t = blockIdx.x;
    int tz = t >> 6, ty = (t >> 3) & 7, tx = t & 7;

    if (tid < 16) { bsum[tid] = 0.f; bsq[tid] = 0.f; }

    for (int i = tid; i < 1000; i += 128) {
        int iz = i / 100, iy = (i / 10) % 10, ix = i % 10;
        int gz = tz * 8 - 1 + iz, gy = ty * 8 - 1 + iy, gx = tx * 8 - 1 + ix;
        float v = 0.f;
        if ((unsigned)gz < 64u && (unsigned)gy < 64u && (unsigned)gx < 64u)
            v = x[((b * 64 + gz) * 64 + gy) * 64 + gx];
        sIn[i] = v;
    }
    for (int i = tid; i < 432; i += 128) sW[i] = w[i];
    __syncthreads();

    int sz = tid >> 4, sy = (tid >> 1) & 7, sx = tid & 1;
    float iv[54];
#pragma unroll
    for (int kd = 0; kd < 3; kd++)
#pragma unroll
        for (int kh = 0; kh < 3; kh++) {
            int base = (sz + kd) * 100 + (sy + kh) * 10 + sx * 4;
#pragma unroll
            for (int u = 0; u < 6; u++) iv[(kd * 3 + kh) * 6 + u] = sIn[base + u];
        }

    int gz = tz * 8 + sz, gy = ty * 8 + sy, gx = tx * 8 + sx * 4;
#pragma unroll 1
    for (int oc = 0; oc < 16; oc++) {
        float a0 = 0.f, a1 = 0.f, a2 = 0.f, a3 = 0.f;
#pragma unroll
        for (int kd = 0; kd < 3; kd++)
#pragma unroll
            for (int kh = 0; kh < 3; kh++)
#pragma unroll
                for (int kw = 0; kw < 3; kw++) {
                    float wv = sW[oc * 27 + (kd * 3 + kh) * 3 + kw];
                    int r = (kd * 3 + kh) * 6 + kw;
                    a0 = fmaf(iv[r], wv, a0);
                    a1 = fmaf(iv[r + 1], wv, a1);
                    a2 = fmaf(iv[r + 2], wv, a2);
                    a3 = fmaf(iv[r + 3], wv, a3);
                }
        float bb = bias[oc];
        a0 += bb; a1 += bb; a2 += bb; a3 += bb;
        float4 o = make_float4(a0, a1, a2, a3);
        *reinterpret_cast<float4*>(&out[(((b * 16 + oc) * 64 + gz) * 64 + gy) * 64 + gx]) = o;

        float s = a0 + a1 + a2 + a3;
        float q = a0 * a0 + a1 * a1 + a2 * a2 + a3 * a3;
#pragma unroll
        for (int off = 16; off > 0; off >>= 1) {
            s += __shfl_down_sync(0xffffffffu, s, off);
            q += __shfl_down_sync(0xffffffffu, q, off);
        }
        if ((tid & 31) == 0) { atomicAdd(&bsum[oc], s); atomicAdd(&bsq[oc], q); }
    }
    __syncthreads();
    if (tid < 16) {
        atomicAdd(&stats[tid], (double)bsum[tid]);
        atomicAdd(&stats[16 + tid], (double)bsq[tid]);
    }
}

// ---------------- conv_s2_v2: stride-2 conv, VPT=4 x-voxels x OCPT ocs per thread ----
// Output tile per block: TZ x TY x (4*TXV). One warp = one oc-group (OCPT ocs)
// over the whole tile. Input rows padded to IXP (mult of 4) -> 2x LDS.128 + 1 LDS.32.
// Applies BN scale/shift + relu of the PREVIOUS stage while loading input to smem.
template <int CIN, int COUTB, int OCPT, int TZ, int TY, int TXV, int ICC>
__global__ void __launch_bounds__(TZ*TY*TXV*(COUTB/OCPT)) conv_s2_v2(
    const float* __restrict__ in, const float* __restrict__ w,
    const float* __restrict__ bias,
    const float* __restrict__ tsc, const float* __restrict__ tsh,
    float* __restrict__ out, double* __restrict__ stats,
    int Din, int Dout, int ntx, int nty, int coutTot) {
    constexpr int VT = TZ * TY * TXV;
    constexpr int GROUPS = COUTB / OCPT;
    constexpr int THREADS = VT * GROUPS;
    constexpr int IZ = 2 * TZ + 1;
    constexpr int IYE = 2 * TY + 1;
    constexpr int IX = 8 * TXV + 1;   // input x extent for 4*TXV outputs
    constexpr int IXP = 8 * TXV + 4;  // padded to multiple of 4 for LDS.128
    constexpr int NIN = ICC * IZ * IYE * IXP;
    constexpr int NW  = COUTB * ICC * 27;
    static_assert(VT == 32, "warp == one oc-group over the full tile");

    extern __shared__ float sm[];
    float* sIn = sm;        // ICC * IZ * IYE * IXP
    float* sW  = sm + NIN;  // COUTB * ICC * 27
    __shared__ float bsum[COUTB], bsq[COUTB];

    int tid = threadIdx.x;
    int b = blockIdx.y;
    int ocBase = blockIdx.z * COUTB;
    int t = blockIdx.x;
    int tx = t % ntx, ty = (t / ntx) % nty, tz = t / (ntx * nty);

    int vt = tid & 31;          // lane
    int group = tid >> 5;       // warp id == oc group
    int oxv = vt % TXV;
    int oy  = (vt / TXV) % TY;
    int oz  = vt / (TXV * TY);

    float acc[OCPT][4];
#pragma unroll
    for (int j = 0; j < OCPT; j++)
#pragma unroll
        for (int u = 0; u < 4; u++) acc[j][u] = 0.f;

    int ginz = tz * (2 * TZ) - 1;
    int giny = ty * (2 * TY) - 1;
    int ginx = tx * (8 * TXV) - 1;   // FIX: input origin for 4*TXV-wide output tile

    for (int c0 = 0; c0 < CIN; c0 += ICC) {
        __syncthreads();
        // load input (with BN+relu of previous stage folded in)
        for (int i = tid; i < NIN; i += THREADS) {
            int ix = i % IXP;
            int r  = i / IXP;
            int iy = r % IYE;
            int r2 = r / IYE;
            int iz = r2 % IZ;
            int ic = r2 / IZ;
            int gz = ginz + iz, gy = giny + iy, gx = ginx + ix;
            float v = 0.f;
            if (ix < IX && (unsigned)gz < (unsigned)Din &&
                (unsigned)gy < (unsigned)Din && (unsigned)gx < (unsigned)Din) {
                v = in[(((b * CIN + c0 + ic) * Din + gz) * Din + gy) * Din + gx];
                v = fmaxf(fmaf(v, tsc[c0 + ic], tsh[c0 + ic]), 0.f);
            }
            sIn[i] = v;
        }
        // load weights
        for (int i = tid; i < NW; i += THREADS) {
            int ocl = i / (ICC * 27), r = i % (ICC * 27);
            sW[i] = w[((ocBase + ocl) * CIN + c0) * 27 + r];
        }
        __syncthreads();

        const float* wg = &sW[group * OCPT * ICC * 27];
#pragma unroll 1
        for (int ic = 0; ic < ICC; ic++) {
#pragma unroll
            for (int kd = 0; kd < 3; kd++)
#pragma unroll
                for (int kh = 0; kh < 3; kh++) {
                    const float* ip =
                        &sIn[((ic * IZ + (2 * oz + kd)) * IYE + (2 * oy + kh)) * IXP +
                             8 * oxv];
                    float4 va = *reinterpret_cast<const float4*>(ip);
                    float4 vb = *reinterpret_cast<const float4*>(ip + 4);
                    float v8 = ip[8];
                    float ivs[9] = {va.x, va.y, va.z, va.w, vb.x, vb.y, vb.z, vb.w, v8};
#pragma unroll
                    for (int j = 0; j < OCPT; j++) {
                        const float* wr = &wg[(j * ICC + ic) * 27 + (kd * 3 + kh) * 3];
                        float w0 = wr[0], w1 = wr[1], w2 = wr[2];
#pragma unroll
                        for (int u = 0; u < 4; u++) {
                            acc[j][u] = fmaf(ivs[2 * u],     w0, acc[j][u]);
                            acc[j][u] = fmaf(ivs[2 * u + 1], w1, acc[j][u]);
                            acc[j][u] = fmaf(ivs[2 * u + 2], w2, acc[j][u]);
                        }
                    }
                }
        }
    }

    int gz = tz * TZ + oz, gy = ty * TY + oy;
    int gx = tx * (4 * TXV) + oxv * 4;   // FIX: output tile x-width is 4*TXV
#pragma unroll
    for (int j = 0; j < OCPT; j++) {
        int oc = ocBase + group * OCPT + j;
        float bb = bias[oc];
        float o0 = acc[j][0] + bb, o1 = acc[j][1] + bb;
        float o2 = acc[j][2] + bb, o3 = acc[j][3] + bb;
        *reinterpret_cast<float4*>(
            &out[(((b * coutTot + oc) * Dout + gz) * Dout + gy) * Dout + gx]) =
            make_float4(o0, o1, o2, o3);

        float s = o0 + o1 + o2 + o3;
        float q = o0 * o0 + o1 * o1 + o2 * o2 + o3 * o3;
#pragma unroll
        for (int off = 16; off > 0; off >>= 1) {
            s += __shfl_down_sync(0xffffffffu, s, off);
            q += __shfl_down_sync(0xffffffffu, q, off);
        }
        if (vt == 0) { bsum[group * OCPT + j] = s; bsq[group * OCPT + j] = q; }
    }
    __syncthreads();
    if (tid < COUTB) {
        atomicAdd(&stats[ocBase + tid], (double)bsum[tid]);
        atomicAdd(&stats[coutTot + ocBase + tid], (double)bsq[tid]);
    }
}

// ---------------- old generic stride-2 conv (kept for tiny stage 4) ----------------
template <int CIN, int COUTB, int OCPT>
__global__ void __launch_bounds__(128) conv_s2_kernel(
    const float* __restrict__ in, const float* __restrict__ w,
    const float* __restrict__ bias,
    const float* __restrict__ tsc, const float* __restrict__ tsh,
    float* __restrict__ out, double* __restrict__ stats,
    int Din, int Dout, int ntile, int coutTot) {
    constexpr int ICC = 16;
    constexpr int NIN = ICC * 729;
    constexpr int NW  = COUTB * ICC * 27;
    extern __shared__ float sm[];
    float* sIn = sm;
    float* sW  = sm + NIN;
    __shared__ float bsum[COUTB], bsq[COUTB];

    int tid = threadIdx.x;
    int b = blockIdx.y;
    int ocBase = blockIdx.z * COUTB;
    int t = blockIdx.x;
    int tz = t / (ntile * ntile), ty = (t / ntile) % ntile, tx = t % ntile;
    int pair = tid & 31, group = tid >> 5;
    int oz = pair >> 3, oy = (pair >> 1) & 3, px = pair & 1;

    if (tid < COUTB) { bsum[tid] = 0.f; bsq[tid] = 0.f; }

    float acc0[OCPT], acc1[OCPT];
#pragma unroll
    for (int j = 0; j < OCPT; j++) { acc0[j] = 0.f; acc1[j] = 0.f; }

    for (int c0 = 0; c0 < CIN; c0 += ICC) {
        __syncthreads();
        for (int i = tid; i < NIN; i += 128) {
            int ic = i / 729, r = i % 729;
            int iz = r / 81, iy = (r / 9) % 9, ix = r % 9;
            int gz = tz * 8 - 1 + iz, gy = ty * 8 - 1 + iy, gx = tx * 8 - 1 + ix;
            float v = 0.f;
            if ((unsigned)gz < (unsigned)Din && (unsigned)gy < (unsigned)Din &&
                (unsigned)gx < (unsigned)Din) {
                v = in[(((b * CIN + c0 + ic) * Din + gz) * Din + gy) * Din + gx];
                v = fmaxf(fmaf(v, tsc[c0 + ic], tsh[c0 + ic]), 0.f);
            }
            sIn[i] = v;
        }
        for (int i = tid; i < NW; i += 128) {
            int ocl = i / (ICC * 27), r = i % (ICC * 27);
            sW[i] = w[((ocBase + ocl) * CIN + c0) * 27 + r];
        }
        __syncthreads();

#pragma unroll 1
        for (int ic = 0; ic < ICC; ic++) {
            const float* wrow = &sW[(group * OCPT) * ICC * 27 + ic * 27];
#pragma unroll
            for (int kd = 0; kd < 3; kd++)
#pragma unroll
                for (int kh = 0; kh < 3; kh++) {
                    int base = ((ic * 9 + (2 * oz + kd)) * 9 + (2 * oy + kh)) * 9 + 4 * px;
                    float ivs[5];
#pragma unroll
                    for (int u = 0; u < 5; u++) ivs[u] = sIn[base + u];
#pragma unroll
                    for (int kw = 0; kw < 3; kw++) {
#pragma unroll
                        for (int j = 0; j < OCPT; j++) {
                            float wv = wrow[j * ICC * 27 + (kd * 3 + kh) * 3 + kw];
                            acc0[j] = fmaf(ivs[kw], wv, acc0[j]);
                            acc1[j] = fmaf(ivs[kw + 2], wv, acc1[j]);
                        }
                    }
                }
        }
    }

    int gz = tz * 4 + oz, gy = ty * 4 + oy, gx = tx * 4 + 2 * px;
#pragma unroll
    for (int j = 0; j < OCPT; j++) {
        int oc = ocBase + group * OCPT + j;
        float bb = bias[oc];
        float o0 = acc0[j] + bb, o1 = acc1[j] + bb;
        float2 o2 = make_float2(o0, o1);
        *reinterpret_cast<float2*>(
            &out[(((b * coutTot + oc) * Dout + gz) * Dout + gy) * Dout + gx]) = o2;

        float s = o0 + o1, q = o0 * o0 + o1 * o1;
#pragma unroll
        for (int off = 16; off > 0; off >>= 1) {
            s += __shfl_down_sync(0xffffffffu, s, off);
            q += __shfl_down_sync(0xffffffffu, q, off);
        }
        if (pair == 0) {
            atomicAdd(&bsum[group * OCPT + j], s);
            atomicAdd(&bsq[group * OCPT + j], q);
        }
    }
    __syncthreads();
    if (tid < COUTB) {
        atomicAdd(&stats[ocBase + tid], (double)bsum[tid]);
        atomicAdd(&stats[coutTot + ocBase + tid], (double)bsq[tid]);
    }
}

// ---------------- heads: 12 dot products + affine matrix composition ----------------
__device__ __forceinline__ void ident4(float* M) {
#pragma unroll
    for (int i = 0; i < 16; i++) M[i] = (i % 5 == 0) ? 1.f : 0.f;
}
__device__ __forceinline__ void mm4(const float* A, const float* B, float* C) {
#pragma unroll
    for (int i = 0; i < 4; i++)
#pragma unroll
        for (int j = 0; j < 4; j++)
            C[i * 4 + j] = A[i * 4 + 0] * B[0 + j] + A[i * 4 + 1] * B[4 + j] +
                           A[i * 4 + 2] * B[8 + j] + A[i * 4 + 3] * B[12 + j];
}

__global__ void __launch_bounds__(256) heads_kernel(
    const float* __restrict__ xs, const float* __restrict__ sc, const float* __restrict__ sh,
    const float* __restrict__ tw, const float* __restrict__ tb,
    const float* __restrict__ rw, const float* __restrict__ rb,
    const float* __restrict__ sw_, const float* __restrict__ sb_,
    const float* __restrict__ shw, const float* __restrict__ shb,
    float* __restrict__ theta) {
    __shared__ float red[12 * 256];
    int b = blockIdx.x, tid = threadIdx.x;
    float p[12];
#pragma unroll
    for (int r = 0; r < 12; r++) p[r] = 0.f;
    for (int i = tid; i < 4096; i += 256) {
        int c = i >> 6;
        float v = fmaxf(fmaf(xs[b * 4096 + i], sc[c], sh[c]), 0.f);
#pragma unroll
        for (int r = 0; r < 3; r++) {
            p[r]     = fmaf(v, tw[r * 4096 + i], p[r]);
            p[3 + r] = fmaf(v, rw[r * 4096 + i], p[3 + r]);
            p[6 + r] = fmaf(v, sw_[r * 4096 + i], p[6 + r]);
            p[9 + r] = fmaf(v, shw[r * 4096 + i], p[9 + r]);
        }
    }
#pragma unroll
    for (int r = 0; r < 12; r++) red[r * 256 + tid] = p[r];
    __syncthreads();
    for (int s = 128; s > 0; s >>= 1) {
        if (tid < s)
#pragma unroll
            for (int r = 0; r < 12; r++) red[r * 256 + tid] += red[r * 256 + tid + s];
        __syncthreads();
    }
    if (tid == 0) {
        const float PI4 = 0.7853981633974483f;
        float tr[3], ro[3], scp[3], shp[3];
#pragma unroll
        for (int r = 0; r < 3; r++) {
            tr[r]  = tanhf(red[r * 256] + tb[r]) * 0.1f;
            ro[r]  = tanhf(red[(3 + r) * 256] + rb[r]) * PI4;
            scp[r] = tanhf(red[(6 + r) * 256] + sb_[r]) * 0.2f;
            shp[r] = tanhf(red[(9 + r) * 256] + shb[r]) * PI4;
        }
        float c0 = cosf(ro[0]), s0 = sinf(ro[0]);
        float c1 = cosf(ro[1]), s1 = sinf(ro[1]);
        float c2 = cosf(ro[2]), s2 = sinf(ro[2]);
        float cs0 = cosf(shp[0]), ss0 = sinf(shp[0]);
        float cs1 = cosf(shp[1]), ss1 = sinf(shp[1]);
        float cs2 = cosf(shp[2]), ss2 = sinf(shp[2]);

        float T[16], R1[16], R2[16], R3[16], S[16], H1[16], H2[16], H3[16];
        float R[16], Sh[16], ShT[16], A[16], B[16];
        ident4(T);  T[3] = tr[0]; T[7] = tr[1]; T[11] = tr[2];
        ident4(R1); R1[0] = c0; R1[1] = -s0; R1[4] = s0; R1[5] = c0;
        ident4(R2); R2[5] = c1; R2[6] = -s1; R2[9] = s1; R2[10] = c1;
        ident4(R3); R3[0] = c2; R3[1] = -s2; R3[4] = s2; R3[5] = c2;
        ident4(S);  S[0] = expf(scp[0]); S[5] = expf(scp[1]); S[10] = expf(scp[2]);
        ident4(H1); H1[5] = cs0; H1[6] = -ss0; H1[9] = ss0; H1[10] = cs0;
        ident4(H2); H2[0] = cs1; H2[2] = ss1; H2[8] = -ss1; H2[10] = cs1;
        ident4(H3); H3[0] = cs2; H3[1] = -ss2; H3[4] = ss2; H3[5] = cs2;

        mm4(R1, R2, A); mm4(A, R3, R);
        mm4(H1, H2, A); mm4(A, H3, Sh);
#pragma unroll
        for (int i = 0; i < 4; i++)
#pragma unroll
            for (int j = 0; j < 4; j++) ShT[i * 4 + j] = Sh[j * 4 + i];
        mm4(Sh, S, A); mm4(A, ShT, B); mm4(B, R, A); mm4(A, T, B);
#pragma unroll
        for (int i = 0; i < 12; i++) theta[b * 12 + i] = B[i];
    }
}

// ---------------- trilinear grid sample (zero padding, clamped gather) ----------------
__global__ void __launch_bounds__(256) sampler_kernel(
    const float* __restrict__ x, const float* __restrict__ theta,
    float* __restrict__ out) {
    int idx = blockIdx.x * 256 + threadIdx.x;
    int b = idx >> 18;
    int r = idx & 262143;
    int z = r >> 12, y = (r >> 6) & 63, xq = r & 63;
    const float st = 2.f / 63.f;
    float xx = fmaf((float)xq, st, -1.f);
    float yy = fmaf((float)y, st, -1.f);
    float zz = fmaf((float)z, st, -1.f);
    const float* th = &theta[b * 12];
    float g0 = th[0] * xx + th[1] * yy + th[2] * zz + th[3];
    float g1 = th[4] * xx + th[5] * yy + th[6] * zz + th[7];
    float g2 = th[8] * xx + th[9] * yy + th[10] * zz + th[11];
    float fx = ((g0 + 1.f) * 64.f - 1.f) * 0.5f;
    float fy = ((g1 + 1.f) * 64.f - 1.f) * 0.5f;
    float fz = ((g2 + 1.f) * 64.f - 1.f) * 0.5f;
    float x0f = floorf(fx), y0f = floorf(fy), z0f = floorf(fz);
    int x0 = (int)x0f, y0 = (int)y0f, z0 = (int)z0f;
    float wx1 = fx - x0f, wx0 = 1.f - wx1;
    float wy1 = fy - y0f, wy0 = 1.f - wy1;
    float wz1 = fz - z0f, wz0 = 1.f - wz1;
    const float* xb = &x[b << 18];
    float acc = 0.f;
#pragma unroll
    for (int dz = 0; dz < 2; dz++) {
        int zc = z0 + dz;
        float wz = dz ? wz1 : wz0;
        bool vz = (zc >= 0 && zc < 64);
        int zi = min(max(zc, 0), 63);
#pragma unroll
        for (int dy = 0; dy < 2; dy++) {
            int yc = y0 + dy;
            float wy = dy ? wy1 : wy0;
            bool vy = vz && (yc >= 0 && yc < 64);
            int yi = min(max(yc, 0), 63);
#pragma unroll
            for (int dx = 0; dx < 2; dx++) {
                int xc = x0 + dx;
                float wgt = wz * wy * (dx ? wx1 : wx0);
                bool v = vy && (xc >= 0 && xc < 64);
                int xi = min(max(xc, 0), 63);
                float val = xb[(zi * 64 + yi) * 64 + xi];
                acc += v ? val * wgt : 0.f;
            }
        }
    }
    out[idx] = acc;
}

// ---------------- launch ----------------
extern "C" void kernel_launch(void* const* d_in, const int* in_sizes, int n_in,
                              void* d_out, int out_size) {
    const float* x    = (const float*)d_in[0];
    const float* w00  = (const float*)d_in[1];
    const float* b00  = (const float*)d_in[2];
    const float* g00  = (const float*)d_in[3];
    const float* be00 = (const float*)d_in[4];
    const float* w0   = (const float*)d_in[5];
    const float* b0   = (const float*)d_in[6];
    const float* g0   = (const float*)d_in[7];
    const float* be0  = (const float*)d_in[8];
    const float* w1   = (const float*)d_in[9];
    const float* b1   = (const float*)d_in[10];
    const float* g1   = (const float*)d_in[11];
    const float* be1  = (const float*)d_in[12];
    const float* w2   = (const float*)d_in[13];
    const float* b2   = (const float*)d_in[14];
    const float* g2   = (const float*)d_in[15];
    const float* be2  = (const float*)d_in[16];
    const float* w3   = (const float*)d_in[17];
    const float* b3   = (const float*)d_in[18];
    const float* g3   = (const float*)d_in[19];
    const float* be3  = (const float*)d_in[20];
    const float* tw   = (const float*)d_in[21];
    const float* tb   = (const float*)d_in[22];
    const float* rw   = (const float*)d_in[23];
    const float* rb   = (const float*)d_in[24];
    const float* sw   = (const float*)d_in[25];
    const float* sb   = (const float*)d_in[26];
    const float* shw  = (const float*)d_in[27];
    const float* shb  = (const float*)d_in[28];

    float *buf0, *buf1, *buf2, *buf3, *buf4, *scale, *shift, *theta;
    double* stats;
    cudaGetSymbolAddress((void**)&buf0, g_buf0);
    cudaGetSymbolAddress((void**)&buf1, g_buf1);
    cudaGetSymbolAddress((void**)&buf2, g_buf2);
    cudaGetSymbolAddress((void**)&buf3, g_buf3);
    cudaGetSymbolAddress((void**)&buf4, g_buf4);
    cudaGetSymbolAddress((void**)&stats, g_stats);
    cudaGetSymbolAddress((void**)&scale, g_scale);
    cudaGetSymbolAddress((void**)&shift, g_shift);
    cudaGetSymbolAddress((void**)&theta, g_theta);

    // smem: (ICC*IZ*IYE*IXP + COUTB*ICC*27) * 4 = (8*9*9*20 + 32*8*27) * 4 = 79488
    const int SM_V2 = (8 * 9 * 9 * 20 + 32 * 8 * 27) * 4;
    const int SM_L3OLD = (16 * 729 + 16 * 16 * 27) * 4;  // 74,304 B (stage 4)
    cudaFuncSetAttribute(conv_s2_v2<16, 32, 8, 4, 4, 2, 8>,
                         cudaFuncAttributeMaxDynamicSharedMemorySize, SM_V2);
    cudaFuncSetAttribute(conv_s2_v2<32, 32, 8, 4, 4, 2, 8>,
                         cudaFuncAttributeMaxDynamicSharedMemorySize, SM_V2);
    cudaFuncSetAttribute(conv_s2_v2<64, 32, 8, 4, 4, 2, 8>,
                         cudaFuncAttributeMaxDynamicSharedMemorySize, SM_V2);
    cudaFuncSetAttribute(conv_s2_kernel<64, 16, 4>,
                         cudaFuncAttributeMaxDynamicSharedMemorySize, SM_L3OLD);

    zero_stats_kernel<<<1, 512>>>(stats);

    // stage 0: conv00 1->16, 64^3
    conv00_kernel<<<dim3(512, 16), 128>>>(x, w00, b00, buf0, stats + 0);
    finalize_kernel<<<1, 64>>>(stats + 0, g00, be00, scale + 0, shift + 0, 16,
                               1.0 / 4194304.0);

    // stage 1: 16->32, 64^3 -> 32^3; tile (4,4,8): ntx=4, nty=8, ntz=8 -> 256 blocks
    conv_s2_v2<16, 32, 8, 4, 4, 2, 8><<<dim3(256, 16, 1), 128, SM_V2>>>(
        buf0, w0, b0, scale + 0, shift + 0, buf1, stats + 32, 64, 32, 4, 8, 32);
    finalize_kernel<<<1, 64>>>(stats + 32, g0, be0, scale + 64, shift + 64, 32,
                               1.0 / 524288.0);

    // stage 2: 32->64, 32^3 -> 16^3; ntx=2, nty=4, ntz=4 -> 32 blocks; oc 2 z-blocks
    conv_s2_v2<32, 32, 8, 4, 4, 2, 8><<<dim3(32, 16, 2), 128, SM_V2>>>(
        buf1, w1, b1, scale + 64, shift + 64, buf2, stats + 96, 32, 16, 2, 4, 64);
    finalize_kernel<<<1, 64>>>(stats + 96, g1, be1, scale + 128, shift + 128, 64,
                               1.0 / 65536.0);

    // stage 3: 64->64, 16^3 -> 8^3; ntx=1, nty=2, ntz=2 -> 4 blocks; oc 2 z-blocks
    conv_s2_v2<64, 32, 8, 4, 4, 2, 8><<<dim3(4, 16, 2), 128, SM_V2>>>(
        buf2, w2, b2, scale + 128, shift + 128, buf3, stats + 224, 16, 8, 1, 2, 64);
    finalize_kernel<<<1, 64>>>(stats + 224, g2, be2, scale + 192, shift + 192, 64,
                               1.0 / 8192.0);

    // stage 4: 64->64, 8^3 -> 4^3 (tiny; old kernel, oc split into 4 z-blocks)
    conv_s2_kernel<64, 16, 4><<<dim3(1, 16, 4), 128, SM_L3OLD>>>(
        buf3, w3, b3, scale + 192, shift + 192, buf4, stats + 352, 8, 4, 1, 64);
    finalize_kernel<<<1, 64>>>(stats + 352, g3, be3, scale + 256, shift + 256, 64,
                               1.0 / 1024.0);

    // heads + affine composition
    heads_kernel<<<16, 256>>>(buf4, scale + 256, shift + 256, tw, tb, rw, rb, sw, sb,
                              shw, shb, theta);

    // grid sample
    sampler_kernel<<<16384, 256>>>(x, theta, (float*)d_out);
}

// round 5
// speedup vs baseline: 1.5420x; 1.2949x over previous
#include <cuda_runtime.h>
#include <math.h>

// ---------------- packed f32x2 helpers (sm_103a FFMA2 path) ----------------
typedef unsigned long long u64t;
__device__ __forceinline__ u64t pack2f(float lo, float hi) {
    u64t r;
    asm("mov.b64 %0, {%1, %2};" : "=l"(r)
        : "r"(__float_as_uint(lo)), "r"(__float_as_uint(hi)));
    return r;
}
__device__ __forceinline__ u64t dup2f(float v) { return pack2f(v, v); }
__device__ __forceinline__ void ffma2(u64t& d, u64t a, u64t b) {
    asm("fma.rn.f32x2 %0, %1, %2, %0;" : "+l"(d) : "l"(a), "l"(b));
}
__device__ __forceinline__ void unpack2f(u64t v, float& lo, float& hi) {
    unsigned ulo, uhi;
    asm("mov.b64 {%0, %1}, %2;" : "=r"(ulo), "=r"(uhi) : "l"(v));
    lo = __uint_as_float(ulo);
    hi = __uint_as_float(uhi);
}

// ---------------- persistent device scratch (no allocations allowed) ----------------
__device__ float  g_buf0[16u*16u*64u*64u*64u];   // conv00 out (raw)   268MB
__device__ float  g_buf1[16u*32u*32u*32u*32u];   // conv0  out (raw)    67MB
__device__ float  g_buf2[16u*64u*16u*16u*16u];   // conv1  out (raw)  16.8MB
__device__ float  g_buf3[16u*64u*8u*8u*8u];      // conv2  out (raw)   2.1MB
__device__ float  g_buf4[16u*64u*4u*4u*4u];      // conv3  out (raw)  0.26MB
__device__ double g_stats[480];                  // per-stage [sum|sumsq]
__device__ float  g_scale[5*64];                 // BN apply: a = g*rsqrt(var+eps)
__device__ float  g_shift[5*64];                 //           b = be - mean*a
__device__ float  g_theta[16*12];                // theta[:, :3, :]

// ---------------- utility kernels ----------------
__global__ void zero_stats_kernel(double* s) {
    int i = threadIdx.x;
    if (i < 480) s[i] = 0.0;
}

__global__ void finalize_kernel(const double* __restrict__ stats,
                                const float* __restrict__ g, const float* __restrict__ be,
                                float* __restrict__ sc, float* __restrict__ sh,
                                int C, double invN) {
    int c = threadIdx.x;
    if (c < C) {
        double mean = stats[c] * invN;
        double var  = stats[C + c] * invN - mean * mean;
        float a = g[c] * (float)(1.0 / sqrt(var + 1e-5));
        sc[c] = a;
        sh[c] = be[c] - (float)mean * a;
    }
}

// ---------------- conv00 v2: 1->16 ch, stride 1, pad 1, 64^3, FFMA2 ----------------
// tile 8^3, 128 threads, each thread: 4 voxels along x, all 16 oc.
// Voxel-pair packing: acc pairs (x0,x1),(x2,x3); weights duplicated (w,w) in smem.
__global__ void __launch_bounds__(128) conv00_v2(
    const float* __restrict__ x, const float* __restrict__ w,
    const float* __restrict__ bias, float* __restrict__ out,
    double* __restrict__ stats) {
    __shared__ float sIn[1000];   // 10^3
    __shared__ float sWd[864];    // 27 * 16 oc * 2 (duplicated)
    __shared__ float bsum[16], bsq[16];

    int tid = threadIdx.x;
    int b = blockIdx.y;
    int t = blockIdx.x;
    int tz = t >> 6, ty = (t >> 3) & 7, tx = t & 7;

    for (int i = tid; i < 1000; i += 128) {
        int iz = i / 100, iy = (i / 10) % 10, ix = i % 10;
        int gz = tz * 8 - 1 + iz, gy = ty * 8 - 1 + iy, gx = tx * 8 - 1 + ix;
        float v = 0.f;
        if ((unsigned)gz < 64u && (unsigned)gy < 64u && (unsigned)gx < 64u)
            v = x[((b * 64 + gz) * 64 + gy) * 64 + gx];
        sIn[i] = v;
    }
    // duplicated weight layout: sWd[k*32 + oc*2 + {0,1}] = w[oc*27 + k]
    for (int i = tid; i < 432; i += 128) {
        int k = i >> 4, oc = i & 15;
        float wv = w[oc * 27 + k];
        sWd[k * 32 + oc * 2]     = wv;
        sWd[k * 32 + oc * 2 + 1] = wv;
    }
    __syncthreads();

    int sz = tid >> 4, sy = (tid >> 1) & 7, sx = tid & 1;

    u64t acc[16][2];  // [oc][pair: (x0,x1),(x2,x3)]
#pragma unroll
    for (int oc = 0; oc < 16; oc++) { acc[oc][0] = 0ULL; acc[oc][1] = 0ULL; }

#pragma unroll
    for (int kd = 0; kd < 3; kd++)
#pragma unroll
        for (int kh = 0; kh < 3; kh++) {
            int base = (sz + kd) * 100 + (sy + kh) * 10 + sx * 4;
            float i0 = sIn[base], i1 = sIn[base + 1], i2 = sIn[base + 2];
            float i3 = sIn[base + 3], i4 = sIn[base + 4], i5 = sIn[base + 5];
            u64t P[5];
            P[0] = pack2f(i0, i1); P[1] = pack2f(i1, i2); P[2] = pack2f(i2, i3);
            P[3] = pack2f(i3, i4); P[4] = pack2f(i4, i5);
            int k9 = kd * 3 + kh;
#pragma unroll
            for (int kw = 0; kw < 3; kw++) {
                const u64t* wrow =
                    reinterpret_cast<const u64t*>(&sWd[(k9 * 3 + kw) * 32]);
#pragma unroll
                for (int oc = 0; oc < 16; oc++) {
                    u64t wp = wrow[oc];
                    ffma2(acc[oc][0], P[kw], wp);
                    ffma2(acc[oc][1], P[kw + 2], wp);
                }
            }
        }

    int gz = tz * 8 + sz, gy = ty * 8 + sy, gx = tx * 8 + sx * 4;
#pragma unroll 1
    for (int oc = 0; oc < 16; oc++) {
        float a0, a1, a2, a3;
        unpack2f(acc[oc][0], a0, a1);
        unpack2f(acc[oc][1], a2, a3);
        float bb = bias[oc];
        a0 += bb; a1 += bb; a2 += bb; a3 += bb;
        *reinterpret_cast<float4*>(&out[(((b * 16 + oc) * 64 + gz) * 64 + gy) * 64 + gx]) =
            make_float4(a0, a1, a2, a3);

        float s = a0 + a1 + a2 + a3;
        float q = a0 * a0 + a1 * a1 + a2 * a2 + a3 * a3;
#pragma unroll
        for (int off = 16; off > 0; off >>= 1) {
            s += __shfl_down_sync(0xffffffffu, s, off);
            q += __shfl_down_sync(0xffffffffu, q, off);
        }
        if ((tid & 31) == 0) { bsum[(oc * 4 + (tid >> 5)) & 15] = 0.f; }  // no-op filler avoided below
        if ((tid & 31) == 0) {
            atomicAdd(&stats[oc], (double)s);
            atomicAdd(&stats[16 + oc], (double)q);
        }
    }
}

// ---------------- conv_s2_v3: stride-2 conv, FFMA2 over oc-pairs -------------------
// Output tile per block: TZ x TY x (4*TXV). One warp = one oc-group (OCPT ocs).
// Weights in smem oc-major: sW[((ic*9+k9)*3+kw)*COUTB + oc] -> LDS.128 = 2 oc-pairs.
// Input duplicated into (v,v) packs in registers. BN+relu of prev stage folded in.
template <int CIN, int COUTB, int OCPT, int TZ, int TY, int TXV, int ICC>
__global__ void __launch_bounds__(TZ*TY*TXV*(COUTB/OCPT)) conv_s2_v3(
    const float* __restrict__ in, const float* __restrict__ w,
    const float* __restrict__ bias,
    const float* __restrict__ tsc, const float* __restrict__ tsh,
    float* __restrict__ out, double* __restrict__ stats,
    int Din, int Dout, int ntx, int nty, int coutTot) {
    constexpr int VT = TZ * TY * TXV;
    constexpr int GROUPS = COUTB / OCPT;
    constexpr int THREADS = VT * GROUPS;
    constexpr int NPAIR = OCPT / 2;   // oc pairs per thread
    constexpr int IZ = 2 * TZ + 1;
    constexpr int IYE = 2 * TY + 1;
    constexpr int IX = 8 * TXV + 1;   // input x extent for 4*TXV outputs
    constexpr int IXP = 8 * TXV + 4;  // padded for LDS.128
    constexpr int NIN = ICC * IZ * IYE * IXP;
    constexpr int NW  = COUTB * ICC * 27;
    static_assert(VT == 32, "warp == one oc-group over the full tile");
    static_assert(NPAIR == 4, "tuned for OCPT=8");

    extern __shared__ float sm[];
    float* sIn = sm;        // ICC * IZ * IYE * IXP
    float* sW  = sm + NIN;  // weights oc-major
    __shared__ float bsum[COUTB], bsq[COUTB];

    int tid = threadIdx.x;
    int b = blockIdx.y;
    int ocBase = blockIdx.z * COUTB;
    int t = blockIdx.x;
    int tx = t % ntx, ty = (t / ntx) % nty, tz = t / (ntx * nty);

    int vt = tid & 31;
    int group = tid >> 5;
    int oxv = vt % TXV;
    int oy  = (vt / TXV) % TY;
    int oz  = vt / (TXV * TY);

    u64t acc[NPAIR][4];  // [oc pair][voxel u]
#pragma unroll
    for (int p = 0; p < NPAIR; p++)
#pragma unroll
        for (int u = 0; u < 4; u++) acc[p][u] = 0ULL;

    int ginz = tz * (2 * TZ) - 1;
    int giny = ty * (2 * TY) - 1;
    int ginx = tx * (8 * TXV) - 1;

    for (int c0 = 0; c0 < CIN; c0 += ICC) {
        __syncthreads();
        // input load (BN+relu folded)
        for (int i = tid; i < NIN; i += THREADS) {
            int ix = i % IXP;
            int r  = i / IXP;
            int iy = r % IYE;
            int r2 = r / IYE;
            int iz = r2 % IZ;
            int ic = r2 / IZ;
            int gz = ginz + iz, gy = giny + iy, gx = ginx + ix;
            float v = 0.f;
            if (ix < IX && (unsigned)gz < (unsigned)Din &&
                (unsigned)gy < (unsigned)Din && (unsigned)gx < (unsigned)Din) {
                v = in[(((b * CIN + c0 + ic) * Din + gz) * Din + gy) * Din + gx];
                v = fmaxf(fmaf(v, tsc[c0 + ic], tsh[c0 + ic]), 0.f);
            }
            sIn[i] = v;
        }
        // weight load, transposed to oc-major
        for (int i = tid; i < NW; i += THREADS) {
            int ocl = i % COUTB;
            int r   = i / COUTB;     // (ic*9+k9)*3+kw
            int kw  = r % 3;
            int t2  = r / 3;
            int k9  = t2 % 9;
            int ic  = t2 / 9;
            sW[i] = w[(ocBase + ocl) * (CIN * 27) + (c0 + ic) * 27 + k9 * 3 + kw];
        }
        __syncthreads();

#pragma unroll 1
        for (int ic = 0; ic < ICC; ic++) {
#pragma unroll
            for (int kd = 0; kd < 3; kd++)
#pragma unroll
                for (int kh = 0; kh < 3; kh++) {
                    const float* ip =
                        &sIn[((ic * IZ + (2 * oz + kd)) * IYE + (2 * oy + kh)) * IXP +
                             8 * oxv];
                    float4 va = *reinterpret_cast<const float4*>(ip);
                    float4 vb = *reinterpret_cast<const float4*>(ip + 4);
                    float v8 = ip[8];
                    u64t ivd[9];
                    ivd[0] = dup2f(va.x); ivd[1] = dup2f(va.y);
                    ivd[2] = dup2f(va.z); ivd[3] = dup2f(va.w);
                    ivd[4] = dup2f(vb.x); ivd[5] = dup2f(vb.y);
                    ivd[6] = dup2f(vb.z); ivd[7] = dup2f(vb.w);
                    ivd[8] = dup2f(v8);
                    int k9 = kd * 3 + kh;
                    const float* wb_ = &sW[((ic * 9 + k9) * 3) * COUTB + group * OCPT];
#pragma unroll
                    for (int kw = 0; kw < 3; kw++) {
                        ulonglong2 wq0 =
                            *reinterpret_cast<const ulonglong2*>(wb_ + kw * COUTB);
                        ulonglong2 wq1 =
                            *reinterpret_cast<const ulonglong2*>(wb_ + kw * COUTB + 4);
#pragma unroll
                        for (int u = 0; u < 4; u++) {
                            u64t iv = ivd[2 * u + kw];
                            ffma2(acc[0][u], wq0.x, iv);
                            ffma2(acc[1][u], wq0.y, iv);
                            ffma2(acc[2][u], wq1.x, iv);
                            ffma2(acc[3][u], wq1.y, iv);
                        }
                    }
                }
        }
    }

    int gz = tz * TZ + oz, gy = ty * TY + oy;
    int gx = tx * (4 * TXV) + oxv * 4;
#pragma unroll
    for (int p = 0; p < NPAIR; p++) {
        float o0[4], o1[4];
#pragma unroll
        for (int u = 0; u < 4; u++) unpack2f(acc[p][u], o0[u], o1[u]);
#pragma unroll
        for (int h = 0; h < 2; h++) {
            float* ov = h ? o1 : o0;
            int ocl = group * OCPT + 2 * p + h;
            int oc = ocBase + ocl;
            float bb = bias[oc];
            float a0 = ov[0] + bb, a1 = ov[1] + bb, a2 = ov[2] + bb, a3 = ov[3] + bb;
            *reinterpret_cast<float4*>(
                &out[(((b * coutTot + oc) * Dout + gz) * Dout + gy) * Dout + gx]) =
                make_float4(a0, a1, a2, a3);

            float s = a0 + a1 + a2 + a3;
            float q = a0 * a0 + a1 * a1 + a2 * a2 + a3 * a3;
#pragma unroll
            for (int off = 16; off > 0; off >>= 1) {
                s += __shfl_down_sync(0xffffffffu, s, off);
                q += __shfl_down_sync(0xffffffffu, q, off);
            }
            if (vt == 0) { bsum[ocl] = s; bsq[ocl] = q; }
        }
    }
    __syncthreads();
    if (tid < COUTB) {
        atomicAdd(&stats[ocBase + tid], (double)bsum[tid]);
        atomicAdd(&stats[coutTot + ocBase + tid], (double)bsq[tid]);
    }
}

// ---------------- old generic stride-2 conv (kept for tiny stage 4) ----------------
template <int CIN, int COUTB, int OCPT>
__global__ void __launch_bounds__(128) conv_s2_kernel(
    const float* __restrict__ in, const float* __restrict__ w,
    const float* __restrict__ bias,
    const float* __restrict__ tsc, const float* __restrict__ tsh,
    float* __restrict__ out, double* __restrict__ stats,
    int Din, int Dout, int ntile, int coutTot) {
    constexpr int ICC = 16;
    constexpr int NIN = ICC * 729;
    constexpr int NW  = COUTB * ICC * 27;
    extern __shared__ float sm[];
    float* sIn = sm;
    float* sW  = sm + NIN;
    __shared__ float bsum[COUTB], bsq[COUTB];

    int tid = threadIdx.x;
    int b = blockIdx.y;
    int ocBase = blockIdx.z * COUTB;
    int t = blockIdx.x;
    int tz = t / (ntile * ntile), ty = (t / ntile) % ntile, tx = t % ntile;
    int pair = tid & 31, group = tid >> 5;
    int oz = pair >> 3, oy = (pair >> 1) & 3, px = pair & 1;

    if (tid < COUTB) { bsum[tid] = 0.f; bsq[tid] = 0.f; }

    float acc0[OCPT], acc1[OCPT];
#pragma unroll
    for (int j = 0; j < OCPT; j++) { acc0[j] = 0.f; acc1[j] = 0.f; }

    for (int c0 = 0; c0 < CIN; c0 += ICC) {
        __syncthreads();
        for (int i = tid; i < NIN; i += 128) {
            int ic = i / 729, r = i % 729;
            int iz = r / 81, iy = (r / 9) % 9, ix = r % 9;
            int gz = tz * 8 - 1 + iz, gy = ty * 8 - 1 + iy, gx = tx * 8 - 1 + ix;
            float v = 0.f;
            if ((unsigned)gz < (unsigned)Din && (unsigned)gy < (unsigned)Din &&
                (unsigned)gx < (unsigned)Din) {
                v = in[(((b * CIN + c0 + ic) * Din + gz) * Din + gy) * Din + gx];
                v = fmaxf(fmaf(v, tsc[c0 + ic], tsh[c0 + ic]), 0.f);
            }
            sIn[i] = v;
        }
        for (int i = tid; i < NW; i += 128) {
            int ocl = i / (ICC * 27), r = i % (ICC * 27);
            sW[i] = w[((ocBase + ocl) * CIN + c0) * 27 + r];
        }
        __syncthreads();

#pragma unroll 1
        for (int ic = 0; ic < ICC; ic++) {
            const float* wrow = &sW[(group * OCPT) * ICC * 27 + ic * 27];
#pragma unroll
            for (int kd = 0; kd < 3; kd++)
#pragma unroll
                for (int kh = 0; kh < 3; kh++) {
                    int base = ((ic * 9 + (2 * oz + kd)) * 9 + (2 * oy + kh)) * 9 + 4 * px;
                    float ivs[5];
#pragma unroll
                    for (int u = 0; u < 5; u++) ivs[u] = sIn[base + u];
#pragma unroll
                    for (int kw = 0; kw < 3; kw++) {
#pragma unroll
                        for (int j = 0; j < OCPT; j++) {
                            float wv = wrow[j * ICC * 27 + (kd * 3 + kh) * 3 + kw];
                            acc0[j] = fmaf(ivs[kw], wv, acc0[j]);
                            acc1[j] = fmaf(ivs[kw + 2], wv, acc1[j]);
                        }
                    }
                }
        }
    }

    int gz = tz * 4 + oz, gy = ty * 4 + oy, gx = tx * 4 + 2 * px;
#pragma unroll
    for (int j = 0; j < OCPT; j++) {
        int oc = ocBase + group * OCPT + j;
        float bb = bias[oc];
        float o0 = acc0[j] + bb, o1 = acc1[j] + bb;
        *reinterpret_cast<float2*>(
            &out[(((b * coutTot + oc) * Dout + gz) * Dout + gy) * Dout + gx]) =
            make_float2(o0, o1);

        float s = o0 + o1, q = o0 * o0 + o1 * o1;
#pragma unroll
        for (int off = 16; off > 0; off >>= 1) {
            s += __shfl_down_sync(0xffffffffu, s, off);
            q += __shfl_down_sync(0xffffffffu, q, off);
        }
        if (pair == 0) {
            atomicAdd(&bsum[group * OCPT + j], s);
            atomicAdd(&bsq[group * OCPT + j], q);
        }
    }
    __syncthreads();
    if (tid < COUTB) {
        atomicAdd(&stats[ocBase + tid], (double)bsum[tid]);
        atomicAdd(&stats[coutTot + ocBase + tid], (double)bsq[tid]);
    }
}

// ---------------- heads: 12 dot products + affine matrix composition ----------------
__device__ __forceinline__ void ident4(float* M) {
#pragma unroll
    for (int i = 0; i < 16; i++) M[i] = (i % 5 == 0) ? 1.f : 0.f;
}
__device__ __forceinline__ void mm4(const float* A, const float* B, float* C) {
#pragma unroll
    for (int i = 0; i < 4; i++)
#pragma unroll
        for (int j = 0; j < 4; j++)
            C[i * 4 + j] = A[i * 4 + 0] * B[0 + j] + A[i * 4 + 1] * B[4 + j] +
                           A[i * 4 + 2] * B[8 + j] + A[i * 4 + 3] * B[12 + j];
}

__global__ void __launch_bounds__(256) heads_kernel(
    const float* __restrict__ xs, const float* __restrict__ sc, const float* __restrict__ sh,
    const float* __restrict__ tw, const float* __restrict__ tb,
    const float* __restrict__ rw, const float* __restrict__ rb,
    const float* __restrict__ sw_, const float* __restrict__ sb_,
    const float* __restrict__ shw, const float* __restrict__ shb,
    float* __restrict__ theta) {
    __shared__ float red[12 * 256];
    int b = blockIdx.x, tid = threadIdx.x;
    float p[12];
#pragma unroll
    for (int r = 0; r < 12; r++) p[r] = 0.f;
    for (int i = tid; i < 4096; i += 256) {
        int c = i >> 6;
        float v = fmaxf(fmaf(xs[b * 4096 + i], sc[c], sh[c]), 0.f);
#pragma unroll
        for (int r = 0; r < 3; r++) {
            p[r]     = fmaf(v, tw[r * 4096 + i], p[r]);
            p[3 + r] = fmaf(v, rw[r * 4096 + i], p[3 + r]);
            p[6 + r] = fmaf(v, sw_[r * 4096 + i], p[6 + r]);
            p[9 + r] = fmaf(v, shw[r * 4096 + i], p[9 + r]);
        }
    }
#pragma unroll
    for (int r = 0; r < 12; r++) red[r * 256 + tid] = p[r];
    __syncthreads();
    for (int s = 128; s > 0; s >>= 1) {
        if (tid < s)
#pragma unroll
            for (int r = 0; r < 12; r++) red[r * 256 + tid] += red[r * 256 + tid + s];
        __syncthreads();
    }
    if (tid == 0) {
        const float PI4 = 0.7853981633974483f;
        float tr[3], ro[3], scp[3], shp[3];
#pragma unroll
        for (int r = 0; r < 3; r++) {
            tr[r]  = tanhf(red[r * 256] + tb[r]) * 0.1f;
            ro[r]  = tanhf(red[(3 + r) * 256] + rb[r]) * PI4;
            scp[r] = tanhf(red[(6 + r) * 256] + sb_[r]) * 0.2f;
            shp[r] = tanhf(red[(9 + r) * 256] + shb[r]) * PI4;
        }
        float c0 = cosf(ro[0]), s0 = sinf(ro[0]);
        float c1 = cosf(ro[1]), s1 = sinf(ro[1]);
        float c2 = cosf(ro[2]), s2 = sinf(ro[2]);
        float cs0 = cosf(shp[0]), ss0 = sinf(shp[0]);
        float cs1 = cosf(shp[1]), ss1 = sinf(shp[1]);
        float cs2 = cosf(shp[2]), ss2 = sinf(shp[2]);

        float T[16], R1[16], R2[16], R3[16], S[16], H1[16], H2[16], H3[16];
        float R[16], Sh[16], ShT[16], A[16], B[16];
        ident4(T);  T[3] = tr[0]; T[7] = tr[1]; T[11] = tr[2];
        ident4(R1); R1[0] = c0; R1[1] = -s0; R1[4] = s0; R1[5] = c0;
        ident4(R2); R2[5] = c1; R2[6] = -s1; R2[9] = s1; R2[10] = c1;
        ident4(R3); R3[0] = c2; R3[1] = -s2; R3[4] = s2; R3[5] = c2;
        ident4(S);  S[0] = expf(scp[0]); S[5] = expf(scp[1]); S[10] = expf(scp[2]);
        ident4(H1); H1[5] = cs0; H1[6] = -ss0; H1[9] = ss0; H1[10] = cs0;
        ident4(H2); H2[0] = cs1; H2[2] = ss1; H2[8] = -ss1; H2[10] = cs1;
        ident4(H3); H3[0] = cs2; H3[1] = -ss2; H3[4] = ss2; H3[5] = cs2;

        mm4(R1, R2, A); mm4(A, R3, R);
        mm4(H1, H2, A); mm4(A, H3, Sh);
#pragma unroll
        for (int i = 0; i < 4; i++)
#pragma unroll
            for (int j = 0; j < 4; j++) ShT[i * 4 + j] = Sh[j * 4 + i];
        mm4(Sh, S, A); mm4(A, ShT, B); mm4(B, R, A); mm4(A, T, B);
#pragma unroll
        for (int i = 0; i < 12; i++) theta[b * 12 + i] = B[i];
    }
}

// ---------------- trilinear grid sample (zero padding, clamped gather) ----------------
__global__ void __launch_bounds__(256) sampler_kernel(
    const float* __restrict__ x, const float* __restrict__ theta,
    float* __restrict__ out) {
    int idx = blockIdx.x * 256 + threadIdx.x;
    int b = idx >> 18;
    int r = idx & 262143;
    int z = r >> 12, y = (r >> 6) & 63, xq = r & 63;
    const float st = 2.f / 63.f;
    float xx = fmaf((float)xq, st, -1.f);
    float yy = fmaf((float)y, st, -1.f);
    float zz = fmaf((float)z, st, -1.f);
    const float* th = &theta[b * 12];
    float g0 = th[0] * xx + th[1] * yy + th[2] * zz + th[3];
    float g1 = th[4] * xx + th[5] * yy + th[6] * zz + th[7];
    float g2 = th[8] * xx + th[9] * yy + th[10] * zz + th[11];
    float fx = ((g0 + 1.f) * 64.f - 1.f) * 0.5f;
    float fy = ((g1 + 1.f) * 64.f - 1.f) * 0.5f;
    float fz = ((g2 + 1.f) * 64.f - 1.f) * 0.5f;
    float x0f = floorf(fx), y0f = floorf(fy), z0f = floorf(fz);
    int x0 = (int)x0f, y0 = (int)y0f, z0 = (int)z0f;
    float wx1 = fx - x0f, wx0 = 1.f - wx1;
    float wy1 = fy - y0f, wy0 = 1.f - wy1;
    float wz1 = fz - z0f, wz0 = 1.f - wz1;
    const float* xb = &x[b << 18];
    float acc = 0.f;
#pragma unroll
    for (int dz = 0; dz < 2; dz++) {
        int zc = z0 + dz;
        float wz = dz ? wz1 : wz0;
        bool vz = (zc >= 0 && zc < 64);
        int zi = min(max(zc, 0), 63);
#pragma unroll
        for (int dy = 0; dy < 2; dy++) {
            int yc = y0 + dy;
            float wy = dy ? wy1 : wy0;
            bool vy = vz && (yc >= 0 && yc < 64);
            int yi = min(max(yc, 0), 63);
#pragma unroll
            for (int dx = 0; dx < 2; dx++) {
                int xc = x0 + dx;
                float wgt = wz * wy * (dx ? wx1 : wx0);
                bool v = vy && (xc >= 0 && xc < 64);
                int xi = min(max(xc, 0), 63);
                float val = xb[(zi * 64 + yi) * 64 + xi];
                acc += v ? val * wgt : 0.f;
            }
        }
    }
    out[idx] = acc;
}

// ---------------- launch ----------------
extern "C" void kernel_launch(void* const* d_in, const int* in_sizes, int n_in,
                              void* d_out, int out_size) {
    const float* x    = (const float*)d_in[0];
    const float* w00  = (const float*)d_in[1];
    const float* b00  = (const float*)d_in[2];
    const float* g00  = (const float*)d_in[3];
    const float* be00 = (const float*)d_in[4];
    const float* w0   = (const float*)d_in[5];
    const float* b0   = (const float*)d_in[6];
    const float* g0   = (const float*)d_in[7];
    const float* be0  = (const float*)d_in[8];
    const float* w1   = (const float*)d_in[9];
    const float* b1   = (const float*)d_in[10];
    const float* g1   = (const float*)d_in[11];
    const float* be1  = (const float*)d_in[12];
    const float* w2   = (const float*)d_in[13];
    const float* b2   = (const float*)d_in[14];
    const float* g2   = (const float*)d_in[15];
    const float* be2  = (const float*)d_in[16];
    const float* w3   = (const float*)d_in[17];
    const float* b3   = (const float*)d_in[18];
    const float* g3   = (const float*)d_in[19];
    const float* be3  = (const float*)d_in[20];
    const float* tw   = (const float*)d_in[21];
    const float* tb   = (const float*)d_in[22];
    const float* rw   = (const float*)d_in[23];
    const float* rb   = (const float*)d_in[24];
    const float* sw   = (const float*)d_in[25];
    const float* sb   = (const float*)d_in[26];
    const float* shw  = (const float*)d_in[27];
    const float* shb  = (const float*)d_in[28];

    float *buf0, *buf1, *buf2, *buf3, *buf4, *scale, *shift, *theta;
    double* stats;
    cudaGetSymbolAddress((void**)&buf0, g_buf0);
    cudaGetSymbolAddress((void**)&buf1, g_buf1);
    cudaGetSymbolAddress((void**)&buf2, g_buf2);
    cudaGetSymbolAddress((void**)&buf3, g_buf3);
    cudaGetSymbolAddress((void**)&buf4, g_buf4);
    cudaGetSymbolAddress((void**)&stats, g_stats);
    cudaGetSymbolAddress((void**)&scale, g_scale);
    cudaGetSymbolAddress((void**)&shift, g_shift);
    cudaGetSymbolAddress((void**)&theta, g_theta);

    // smem v3: (ICC*IZ*IYE*IXP + COUTB*ICC*27)*4 = (4*9*9*20 + 32*4*27)*4 = 39744
    const int SM_V3 = (4 * 9 * 9 * 20 + 32 * 4 * 27) * 4;
    const int SM_L3OLD = (16 * 729 + 16 * 16 * 27) * 4;  // 74,304 B (stage 4)
    cudaFuncSetAttribute(conv_s2_v3<16, 32, 8, 4, 4, 2, 4>,
                         cudaFuncAttributeMaxDynamicSharedMemorySize, SM_V3);
    cudaFuncSetAttribute(conv_s2_v3<32, 32, 8, 4, 4, 2, 4>,
                         cudaFuncAttributeMaxDynamicSharedMemorySize, SM_V3);
    cudaFuncSetAttribute(conv_s2_v3<64, 32, 8, 4, 4, 2, 4>,
                         cudaFuncAttributeMaxDynamicSharedMemorySize, SM_V3);
    cudaFuncSetAttribute(conv_s2_kernel<64, 16, 4>,
                         cudaFuncAttributeMaxDynamicSharedMemorySize, SM_L3OLD);

    zero_stats_kernel<<<1, 512>>>(stats);

    // stage 0: conv00 1->16, 64^3 (FFMA2)
    conv00_v2<<<dim3(512, 16), 128>>>(x, w00, b00, buf0, stats + 0);
    finalize_kernel<<<1, 64>>>(stats + 0, g00, be00, scale + 0, shift + 0, 16,
                               1.0 / 4194304.0);

    // stage 1: 16->32, 64^3 -> 32^3; tile (4,4,8): ntx=4, nty=8, ntz=8 -> 256 blocks
    conv_s2_v3<16, 32, 8, 4, 4, 2, 4><<<dim3(256, 16, 1), 128, SM_V3>>>(
        buf0, w0, b0, scale + 0, shift + 0, buf1, stats + 32, 64, 32, 4, 8, 32);
    finalize_kernel<<<1, 64>>>(stats + 32, g0, be0, scale + 64, shift + 64, 32,
                               1.0 / 524288.0);

    // stage 2: 32->64, 32^3 -> 16^3; ntx=2, nty=4, ntz=4 -> 32 blocks; oc 2 z-blocks
    conv_s2_v3<32, 32, 8, 4, 4, 2, 4><<<dim3(32, 16, 2), 128, SM_V3>>>(
        buf1, w1, b1, scale + 64, shift + 64, buf2, stats + 96, 32, 16, 2, 4, 64);
    finalize_kernel<<<1, 64>>>(stats + 96, g1, be1, scale + 128, shift + 128, 64,
                               1.0 / 65536.0);

    // stage 3: 64->64, 16^3 -> 8^3; ntx=1, nty=2, ntz=2 -> 4 blocks; oc 2 z-blocks
    conv_s2_v3<64, 32, 8, 4, 4, 2, 4><<<dim3(4, 16, 2), 128, SM_V3>>>(
        buf2, w2, b2, scale + 128, shift + 128, buf3, stats + 224, 16, 8, 1, 2, 64);
    finalize_kernel<<<1, 64>>>(stats + 224, g2, be2, scale + 192, shift + 192, 64,
                               1.0 / 8192.0);

    // stage 4: 64->64, 8^3 -> 4^3 (tiny; old kernel, oc split into 4 z-blocks)
    conv_s2_kernel<64, 16, 4><<<dim3(1, 16, 4), 128, SM_L3OLD>>>(
        buf3, w3, b3, scale + 192, shift + 192, buf4, stats + 352, 8, 4, 1, 64);
    finalize_kernel<<<1, 64>>>(stats + 352, g3, be3, scale + 256, shift + 256, 64,
                               1.0 / 1024.0);

    // heads + affine composition
    heads_kernel<<<16, 256>>>(buf4, scale + 256, shift + 256, tw, tb, rw, rb, sw, sb,
                              shw, shb, theta);

    // grid sample
    sampler_kernel<<<16384, 256>>>(x, theta, (float*)d_out);
}

// round 6
// speedup vs baseline: 1.6907x; 1.0964x over previous
#include <cuda_runtime.h>
#include <math.h>

// ---------------- packed f32x2 helpers (sm_103a FFMA2 path) ----------------
typedef unsigned long long u64t;
__device__ __forceinline__ u64t pack2f(float lo, float hi) {
    u64t r;
    asm("mov.b64 %0, {%1, %2};" : "=l"(r)
        : "r"(__float_as_uint(lo)), "r"(__float_as_uint(hi)));
    return r;
}
__device__ __forceinline__ void ffma2(u64t& d, u64t a, u64t b) {
    asm("fma.rn.f32x2 %0, %1, %2, %0;" : "+l"(d) : "l"(a), "l"(b));
}
__device__ __forceinline__ void unpack2f(u64t v, float& lo, float& hi) {
    unsigned ulo, uhi;
    asm("mov.b64 {%0, %1}, %2;" : "=r"(ulo), "=r"(uhi) : "l"(v));
    lo = __uint_as_float(ulo);
    hi = __uint_as_float(uhi);
}

// ---------------- persistent device scratch (no allocations allowed) ----------------
__device__ float  g_buf0[16u*16u*64u*64u*64u];   // conv00 out (raw)   268MB
__device__ float  g_buf1[16u*32u*32u*32u*32u];   // conv0  out (raw)    67MB
__device__ float  g_buf2[16u*64u*16u*16u*16u];   // conv1  out (raw)  16.8MB
__device__ float  g_buf3[16u*64u*8u*8u*8u];      // conv2  out (raw)   2.1MB
__device__ float  g_buf4[16u*64u*4u*4u*4u];      // conv3  out (raw)  0.26MB
__device__ double g_stats[480];                  // per-stage [sum|sumsq]
__device__ float  g_scale[5*64];                 // BN apply: a = g*rsqrt(var+eps)
__device__ float  g_shift[5*64];                 //           b = be - mean*a
__device__ float  g_theta[16*12];                // theta[:, :3, :]

// ---------------- utility kernels ----------------
__global__ void zero_stats_kernel(double* s) {
    int i = threadIdx.x;
    if (i < 480) s[i] = 0.0;
}

__global__ void finalize_kernel(const double* __restrict__ stats,
                                const float* __restrict__ g, const float* __restrict__ be,
                                float* __restrict__ sc, float* __restrict__ sh,
                                int C, double invN) {
    int c = threadIdx.x;
    if (c < C) {
        double mean = stats[c] * invN;
        double var  = stats[C + c] * invN - mean * mean;
        float a = g[c] * (float)(1.0 / sqrt(var + 1e-5));
        sc[c] = a;
        sh[c] = be[c] - (float)mean * a;
    }
}

// ---------------- conv00 v2: 1->16 ch, stride 1, pad 1, 64^3, FFMA2 ----------------
__global__ void __launch_bounds__(128) conv00_v2(
    const float* __restrict__ x, const float* __restrict__ w,
    const float* __restrict__ bias, float* __restrict__ out,
    double* __restrict__ stats) {
    __shared__ float sIn[1000];   // 10^3
    __shared__ float sWd[864];    // 27 * 16 oc * 2 (duplicated)

    int tid = threadIdx.x;
    int b = blockIdx.y;
    int t = blockIdx.x;
    int tz = t >> 6, ty = (t >> 3) & 7, tx = t & 7;

    for (int i = tid; i < 1000; i += 128) {
        int iz = i / 100, iy = (i / 10) % 10, ix = i % 10;
        int gz = tz * 8 - 1 + iz, gy = ty * 8 - 1 + iy, gx = tx * 8 - 1 + ix;
        float v = 0.f;
        if ((unsigned)gz < 64u && (unsigned)gy < 64u && (unsigned)gx < 64u)
            v = x[((b * 64 + gz) * 64 + gy) * 64 + gx];
        sIn[i] = v;
    }
    for (int i = tid; i < 432; i += 128) {
        int k = i >> 4, oc = i & 15;
        float wv = w[oc * 27 + k];
        sWd[k * 32 + oc * 2]     = wv;
        sWd[k * 32 + oc * 2 + 1] = wv;
    }
    __syncthreads();

    int sz = tid >> 4, sy = (tid >> 1) & 7, sx = tid & 1;

    u64t acc[16][2];
#pragma unroll
    for (int oc = 0; oc < 16; oc++) { acc[oc][0] = 0ULL; acc[oc][1] = 0ULL; }

#pragma unroll
    for (int kd = 0; kd < 3; kd++)
#pragma unroll
        for (int kh = 0; kh < 3; kh++) {
            int base = (sz + kd) * 100 + (sy + kh) * 10 + sx * 4;
            float i0 = sIn[base], i1 = sIn[base + 1], i2 = sIn[base + 2];
            float i3 = sIn[base + 3], i4 = sIn[base + 4], i5 = sIn[base + 5];
            u64t P[5];
            P[0] = pack2f(i0, i1); P[1] = pack2f(i1, i2); P[2] = pack2f(i2, i3);
            P[3] = pack2f(i3, i4); P[4] = pack2f(i4, i5);
            int k9 = kd * 3 + kh;
#pragma unroll
            for (int kw = 0; kw < 3; kw++) {
                const u64t* wrow =
                    reinterpret_cast<const u64t*>(&sWd[(k9 * 3 + kw) * 32]);
#pragma unroll
                for (int oc = 0; oc < 16; oc++) {
                    u64t wp = wrow[oc];
                    ffma2(acc[oc][0], P[kw], wp);
                    ffma2(acc[oc][1], P[kw + 2], wp);
                }
            }
        }

    int gz = tz * 8 + sz, gy = ty * 8 + sy, gx = tx * 8 + sx * 4;
#pragma unroll 1
    for (int oc = 0; oc < 16; oc++) {
        float a0, a1, a2, a3;
        unpack2f(acc[oc][0], a0, a1);
        unpack2f(acc[oc][1], a2, a3);
        float bb = bias[oc];
        a0 += bb; a1 += bb; a2 += bb; a3 += bb;
        *reinterpret_cast<float4*>(&out[(((b * 16 + oc) * 64 + gz) * 64 + gy) * 64 + gx]) =
            make_float4(a0, a1, a2, a3);

        float s = a0 + a1 + a2 + a3;
        float q = a0 * a0 + a1 * a1 + a2 * a2 + a3 * a3;
#pragma unroll
        for (int off = 16; off > 0; off >>= 1) {
            s += __shfl_down_sync(0xffffffffu, s, off);
            q += __shfl_down_sync(0xffffffffu, q, off);
        }
        if ((tid & 31) == 0) {
            atomicAdd(&stats[oc], (double)s);
            atomicAdd(&stats[16 + oc], (double)q);
        }
    }
}

// ---------------- conv_s2_v4: stride-2 conv, FFMA2, dup-input smem ----------------
// Input stored in smem as duplicated (v,v) u64 pairs -> inner loop has ZERO pack MOVs:
// 4x LDS.128 + 1x LDS.64 input, 2x LDS.128 weights (broadcast) per (ic,k9).
// Weights oc-major. BN+relu of prev stage folded into loader.
template <int CIN, int COUTB, int OCPT, int TZ, int TY, int TXV, int ICC>
__global__ void __launch_bounds__(TZ*TY*TXV*(COUTB/OCPT)) conv_s2_v4(
    const float* __restrict__ in, const float* __restrict__ w,
    const float* __restrict__ bias,
    const float* __restrict__ tsc, const float* __restrict__ tsh,
    float* __restrict__ out, double* __restrict__ stats,
    int Din, int Dout, int ntx, int nty, int coutTot) {
    constexpr int VT = TZ * TY * TXV;
    constexpr int GROUPS = COUTB / OCPT;
    constexpr int THREADS = VT * GROUPS;
    constexpr int NPAIR = OCPT / 2;
    constexpr int IZ = 2 * TZ + 1;
    constexpr int IYE = 2 * TY + 1;
    constexpr int IX = 8 * TXV + 1;    // 17 input x positions
    constexpr int IXP2 = 8 * TXV + 2;  // u64 entries per row (18, even for 16B align)
    constexpr int NIN = ICC * IZ * IYE * IXP2;  // u64 count
    constexpr int NW  = COUTB * ICC * 27;
    static_assert(VT == 32, "warp == one oc-group over the full tile");
    static_assert(NPAIR == 4, "tuned for OCPT=8");
    static_assert((IXP2 & 1) == 0, "row stride must be even u64s");

    extern __shared__ float sm[];
    u64t*  sInD = reinterpret_cast<u64t*>(sm);       // NIN u64
    float* sW   = sm + 2 * NIN;                       // oc-major weights
    __shared__ float bsum[COUTB], bsq[COUTB];

    int tid = threadIdx.x;
    int b = blockIdx.y;
    int ocBase = blockIdx.z * COUTB;
    int t = blockIdx.x;
    int tx = t % ntx, ty = (t / ntx) % nty, tz = t / (ntx * nty);

    int vt = tid & 31;
    int group = tid >> 5;
    int oxv = vt % TXV;
    int oy  = (vt / TXV) % TY;
    int oz  = vt / (TXV * TY);

    u64t acc[NPAIR][4];
#pragma unroll
    for (int p = 0; p < NPAIR; p++)
#pragma unroll
        for (int u = 0; u < 4; u++) acc[p][u] = 0ULL;

    int ginz = tz * (2 * TZ) - 1;
    int giny = ty * (2 * TY) - 1;
    int ginx = tx * (8 * TXV) - 1;

    for (int c0 = 0; c0 < CIN; c0 += ICC) {
        __syncthreads();
        // input load (BN+relu folded), store duplicated (v,v)
        for (int i = tid; i < NIN; i += THREADS) {
            int ix = i % IXP2;
            int r  = i / IXP2;
            int iy = r % IYE;
            int r2 = r / IYE;
            int iz = r2 % IZ;
            int ic = r2 / IZ;
            int gz = ginz + iz, gy = giny + iy, gx = ginx + ix;
            float v = 0.f;
            if (ix < IX && (unsigned)gz < (unsigned)Din &&
                (unsigned)gy < (unsigned)Din && (unsigned)gx < (unsigned)Din) {
                v = in[(((b * CIN + c0 + ic) * Din + gz) * Din + gy) * Din + gx];
                v = fmaxf(fmaf(v, tsc[c0 + ic], tsh[c0 + ic]), 0.f);
            }
            sInD[i] = pack2f(v, v);
        }
        // weight load, transposed to oc-major
        for (int i = tid; i < NW; i += THREADS) {
            int ocl = i % COUTB;
            int r   = i / COUTB;     // (ic*9+k9)*3+kw
            int kw  = r % 3;
            int t2  = r / 3;
            int k9  = t2 % 9;
            int ic  = t2 / 9;
            sW[i] = w[(ocBase + ocl) * (CIN * 27) + (c0 + ic) * 27 + k9 * 3 + kw];
        }
        __syncthreads();

#pragma unroll
        for (int ic = 0; ic < ICC; ic++) {
#pragma unroll
            for (int kd = 0; kd < 3; kd++)
#pragma unroll
                for (int kh = 0; kh < 3; kh++) {
                    const u64t* ip =
                        &sInD[((ic * IZ + (2 * oz + kd)) * IYE + (2 * oy + kh)) * IXP2 +
                              8 * oxv];
                    ulonglong2 q0 = *reinterpret_cast<const ulonglong2*>(ip);
                    ulonglong2 q1 = *reinterpret_cast<const ulonglong2*>(ip + 2);
                    ulonglong2 q2 = *reinterpret_cast<const ulonglong2*>(ip + 4);
                    ulonglong2 q3 = *reinterpret_cast<const ulonglong2*>(ip + 6);
                    u64t iv8 = ip[8];
                    u64t ivd[9] = {q0.x, q0.y, q1.x, q1.y, q2.x, q2.y, q3.x, q3.y, iv8};
                    int k9 = kd * 3 + kh;
                    const float* wb_ = &sW[((ic * 9 + k9) * 3) * COUTB + group * OCPT];
#pragma unroll
                    for (int kw = 0; kw < 3; kw++) {
                        ulonglong2 wq0 =
                            *reinterpret_cast<const ulonglong2*>(wb_ + kw * COUTB);
                        ulonglong2 wq1 =
                            *reinterpret_cast<const ulonglong2*>(wb_ + kw * COUTB + 4);
#pragma unroll
                        for (int u = 0; u < 4; u++) {
                            u64t iv = ivd[2 * u + kw];
                            ffma2(acc[0][u], wq0.x, iv);
                            ffma2(acc[1][u], wq0.y, iv);
                            ffma2(acc[2][u], wq1.x, iv);
                            ffma2(acc[3][u], wq1.y, iv);
                        }
                    }
                }
        }
    }

    int gz = tz * TZ + oz, gy = ty * TY + oy;
    int gx = tx * (4 * TXV) + oxv * 4;
#pragma unroll
    for (int p = 0; p < NPAIR; p++) {
        float o0[4], o1[4];
#pragma unroll
        for (int u = 0; u < 4; u++) unpack2f(acc[p][u], o0[u], o1[u]);
#pragma unroll
        for (int h = 0; h < 2; h++) {
            float* ov = h ? o1 : o0;
            int ocl = group * OCPT + 2 * p + h;
            int oc = ocBase + ocl;
            float bb = bias[oc];
            float a0 = ov[0] + bb, a1 = ov[1] + bb, a2 = ov[2] + bb, a3 = ov[3] + bb;
            *reinterpret_cast<float4*>(
                &out[(((b * coutTot + oc) * Dout + gz) * Dout + gy) * Dout + gx]) =
                make_float4(a0, a1, a2, a3);

            float s = a0 + a1 + a2 + a3;
            float q = a0 * a0 + a1 * a1 + a2 * a2 + a3 * a3;
#pragma unroll
            for (int off = 16; off > 0; off >>= 1) {
                s += __shfl_down_sync(0xffffffffu, s, off);
                q += __shfl_down_sync(0xffffffffu, q, off);
            }
            if (vt == 0) { bsum[ocl] = s; bsq[ocl] = q; }
        }
    }
    __syncthreads();
    if (tid < COUTB) {
        atomicAdd(&stats[ocBase + tid], (double)bsum[tid]);
        atomicAdd(&stats[coutTot + ocBase + tid], (double)bsq[tid]);
    }
}

// ---------------- old generic stride-2 conv (kept for tiny stage 4) ----------------
template <int CIN, int COUTB, int OCPT>
__global__ void __launch_bounds__(128) conv_s2_kernel(
    const float* __restrict__ in, const float* __restrict__ w,
    const float* __restrict__ bias,
    const float* __restrict__ tsc, const float* __restrict__ tsh,
    float* __restrict__ out, double* __restrict__ stats,
    int Din, int Dout, int ntile, int coutTot) {
    constexpr int ICC = 16;
    constexpr int NIN = ICC * 729;
    constexpr int NW  = COUTB * ICC * 27;
    extern __shared__ float sm[];
    float* sIn = sm;
    float* sW  = sm + NIN;
    __shared__ float bsum[COUTB], bsq[COUTB];

    int tid = threadIdx.x;
    int b = blockIdx.y;
    int ocBase = blockIdx.z * COUTB;
    int t = blockIdx.x;
    int tz = t / (ntile * ntile), ty = (t / ntile) % ntile, tx = t % ntile;
    int pair = tid & 31, group = tid >> 5;
    int oz = pair >> 3, oy = (pair >> 1) & 3, px = pair & 1;

    if (tid < COUTB) { bsum[tid] = 0.f; bsq[tid] = 0.f; }

    float acc0[OCPT], acc1[OCPT];
#pragma unroll
    for (int j = 0; j < OCPT; j++) { acc0[j] = 0.f; acc1[j] = 0.f; }

    for (int c0 = 0; c0 < CIN; c0 += ICC) {
        __syncthreads();
        for (int i = tid; i < NIN; i += 128) {
            int ic = i / 729, r = i % 729;
            int iz = r / 81, iy = (r / 9) % 9, ix = r % 9;
            int gz = tz * 8 - 1 + iz, gy = ty * 8 - 1 + iy, gx = tx * 8 - 1 + ix;
            float v = 0.f;
            if ((unsigned)gz < (unsigned)Din && (unsigned)gy < (unsigned)Din &&
                (unsigned)gx < (unsigned)Din) {
                v = in[(((b * CIN + c0 + ic) * Din + gz) * Din + gy) * Din + gx];
                v = fmaxf(fmaf(v, tsc[c0 + ic], tsh[c0 + ic]), 0.f);
            }
            sIn[i] = v;
        }
        for (int i = tid; i < NW; i += 128) {
            int ocl = i / (ICC * 27), r = i % (ICC * 27);
            sW[i] = w[((ocBase + ocl) * CIN + c0) * 27 + r];
        }
        __syncthreads();

#pragma unroll 1
        for (int ic = 0; ic < ICC; ic++) {
            const float* wrow = &sW[(group * OCPT) * ICC * 27 + ic * 27];
#pragma unroll
            for (int kd = 0; kd < 3; kd++)
#pragma unroll
                for (int kh = 0; kh < 3; kh++) {
                    int base = ((ic * 9 + (2 * oz + kd)) * 9 + (2 * oy + kh)) * 9 + 4 * px;
                    float ivs[5];
#pragma unroll
                    for (int u = 0; u < 5; u++) ivs[u] = sIn[base + u];
#pragma unroll
                    for (int kw = 0; kw < 3; kw++) {
#pragma unroll
                        for (int j = 0; j < OCPT; j++) {
                            float wv = wrow[j * ICC * 27 + (kd * 3 + kh) * 3 + kw];
                            acc0[j] = fmaf(ivs[kw], wv, acc0[j]);
                            acc1[j] = fmaf(ivs[kw + 2], wv, acc1[j]);
                        }
                    }
                }
        }
    }

    int gz = tz * 4 + oz, gy = ty * 4 + oy, gx = tx * 4 + 2 * px;
#pragma unroll
    for (int j = 0; j < OCPT; j++) {
        int oc = ocBase + group * OCPT + j;
        float bb = bias[oc];
        float o0 = acc0[j] + bb, o1 = acc1[j] + bb;
        *reinterpret_cast<float2*>(
            &out[(((b * coutTot + oc) * Dout + gz) * Dout + gy) * Dout + gx]) =
            make_float2(o0, o1);

        float s = o0 + o1, q = o0 * o0 + o1 * o1;
#pragma unroll
        for (int off = 16; off > 0; off >>= 1) {
            s += __shfl_down_sync(0xffffffffu, s, off);
            q += __shfl_down_sync(0xffffffffu, q, off);
        }
        if (pair == 0) {
            atomicAdd(&bsum[group * OCPT + j], s);
            atomicAdd(&bsq[group * OCPT + j], q);
        }
    }
    __syncthreads();
    if (tid < COUTB) {
        atomicAdd(&stats[ocBase + tid], (double)bsum[tid]);
        atomicAdd(&stats[coutTot + ocBase + tid], (double)bsq[tid]);
    }
}

// ---------------- heads: 12 dot products + affine matrix composition ----------------
__device__ __forceinline__ void ident4(float* M) {
#pragma unroll
    for (int i = 0; i < 16; i++) M[i] = (i % 5 == 0) ? 1.f : 0.f;
}
__device__ __forceinline__ void mm4(const float* A, const float* B, float* C) {
#pragma unroll
    for (int i = 0; i < 4; i++)
#pragma unroll
        for (int j = 0; j < 4; j++)
            C[i * 4 + j] = A[i * 4 + 0] * B[0 + j] + A[i * 4 + 1] * B[4 + j] +
                           A[i * 4 + 2] * B[8 + j] + A[i * 4 + 3] * B[12 + j];
}

__global__ void __launch_bounds__(256) heads_kernel(
    const float* __restrict__ xs, const float* __restrict__ sc, const float* __restrict__ sh,
    const float* __restrict__ tw, const float* __restrict__ tb,
    const float* __restrict__ rw, const float* __restrict__ rb,
    const float* __restrict__ sw_, const float* __restrict__ sb_,
    const float* __restrict__ shw, const float* __restrict__ shb,
    float* __restrict__ theta) {
    __shared__ float red[12 * 256];
    int b = blockIdx.x, tid = threadIdx.x;
    float p[12];
#pragma unroll
    for (int r = 0; r < 12; r++) p[r] = 0.f;
    for (int i = tid; i < 4096; i += 256) {
        int c = i >> 6;
        float v = fmaxf(fmaf(xs[b * 4096 + i], sc[c], sh[c]), 0.f);
#pragma unroll
        for (int r = 0; r < 3; r++) {
            p[r]     = fmaf(v, tw[r * 4096 + i], p[r]);
            p[3 + r] = fmaf(v, rw[r * 4096 + i], p[3 + r]);
            p[6 + r] = fmaf(v, sw_[r * 4096 + i], p[6 + r]);
            p[9 + r] = fmaf(v, shw[r * 4096 + i], p[9 + r]);
        }
    }
#pragma unroll
    for (int r = 0; r < 12; r++) red[r * 256 + tid] = p[r];
    __syncthreads();
    for (int s = 128; s > 0; s >>= 1) {
        if (tid < s)
#pragma unroll
            for (int r = 0; r < 12; r++) red[r * 256 + tid] += red[r * 256 + tid + s];
        __syncthreads();
    }
    if (tid == 0) {
        const float PI4 = 0.7853981633974483f;
        float tr[3], ro[3], scp[3], shp[3];
#pragma unroll
        for (int r = 0; r < 3; r++) {
            tr[r]  = tanhf(red[r * 256] + tb[r]) * 0.1f;
            ro[r]  = tanhf(red[(3 + r) * 256] + rb[r]) * PI4;
            scp[r] = tanhf(red[(6 + r) * 256] + sb_[r]) * 0.2f;
            shp[r] = tanhf(red[(9 + r) * 256] + shb[r]) * PI4;
        }
        float c0 = cosf(ro[0]), s0 = sinf(ro[0]);
        float c1 = cosf(ro[1]), s1 = sinf(ro[1]);
        float c2 = cosf(ro[2]), s2 = sinf(ro[2]);
        float cs0 = cosf(shp[0]), ss0 = sinf(shp[0]);
        float cs1 = cosf(shp[1]), ss1 = sinf(shp[1]);
        float cs2 = cosf(shp[2]), ss2 = sinf(shp[2]);

        float T[16], R1[16], R2[16], R3[16], S[16], H1[16], H2[16], H3[16];
        float R[16], Sh[16], ShT[16], A[16], B[16];
        ident4(T);  T[3] = tr[0]; T[7] = tr[1]; T[11] = tr[2];
        ident4(R1); R1[0] = c0; R1[1] = -s0; R1[4] = s0; R1[5] = c0;
        ident4(R2); R2[5] = c1; R2[6] = -s1; R2[9] = s1; R2[10] = c1;
        ident4(R3); R3[0] = c2; R3[1] = -s2; R3[4] = s2; R3[5] = c2;
        ident4(S);  S[0] = expf(scp[0]); S[5] = expf(scp[1]); S[10] = expf(scp[2]);
        ident4(H1); H1[5] = cs0; H1[6] = -ss0; H1[9] = ss0; H1[10] = cs0;
        ident4(H2); H2[0] = cs1; H2[2] = ss1; H2[8] = -ss1; H2[10] = cs1;
        ident4(H3); H3[0] = cs2; H3[1] = -ss2; H3[4] = ss2; H3[5] = cs2;

        mm4(R1, R2, A); mm4(A, R3, R);
        mm4(H1, H2, A); mm4(A, H3, Sh);
#pragma unroll
        for (int i = 0; i < 4; i++)
#pragma unroll
            for (int j = 0; j < 4; j++) ShT[i * 4 + j] = Sh[j * 4 + i];
        mm4(Sh, S, A); mm4(A, ShT, B); mm4(B, R, A); mm4(A, T, B);
#pragma unroll
        for (int i = 0; i < 12; i++) theta[b * 12 + i] = B[i];
    }
}

// ---------------- trilinear grid sample (zero padding, clamped gather) ----------------
__global__ void __launch_bounds__(256) sampler_kernel(
    const float* __restrict__ x, const float* __restrict__ theta,
    float* __restrict__ out) {
    int idx = blockIdx.x * 256 + threadIdx.x;
    int b = idx >> 18;
    int r = idx & 262143;
    int z = r >> 12, y = (r >> 6) & 63, xq = r & 63;
    const float st = 2.f / 63.f;
    float xx = fmaf((float)xq, st, -1.f);
    float yy = fmaf((float)y, st, -1.f);
    float zz = fmaf((float)z, st, -1.f);
    const float* th = &theta[b * 12];
    float g0 = th[0] * xx + th[1] * yy + th[2] * zz + th[3];
    float g1 = th[4] * xx + th[5] * yy + th[6] * zz + th[7];
    float g2 = th[8] * xx + th[9] * yy + th[10] * zz + th[11];
    float fx = ((g0 + 1.f) * 64.f - 1.f) * 0.5f;
    float fy = ((g1 + 1.f) * 64.f - 1.f) * 0.5f;
    float fz = ((g2 + 1.f) * 64.f - 1.f) * 0.5f;
    float x0f = floorf(fx), y0f = floorf(fy), z0f = floorf(fz);
    int x0 = (int)x0f, y0 = (int)y0f, z0 = (int)z0f;
    float wx1 = fx - x0f, wx0 = 1.f - wx1;
    float wy1 = fy - y0f, wy0 = 1.f - wy1;
    float wz1 = fz - z0f, wz0 = 1.f - wz1;
    const float* xb = &x[b << 18];
    float acc = 0.f;
#pragma unroll
    for (int dz = 0; dz < 2; dz++) {
        int zc = z0 + dz;
        float wz = dz ? wz1 : wz0;
        bool vz = (zc >= 0 && zc < 64);
        int zi = min(max(zc, 0), 63);
#pragma unroll
        for (int dy = 0; dy < 2; dy++) {
            int yc = y0 + dy;
            float wy = dy ? wy1 : wy0;
            bool vy = vz && (yc >= 0 && yc < 64);
            int yi = min(max(yc, 0), 63);
#pragma unroll
            for (int dx = 0; dx < 2; dx++) {
                int xc = x0 + dx;
                float wgt = wz * wy * (dx ? wx1 : wx0);
                bool v = vy && (xc >= 0 && xc < 64);
                int xi = min(max(xc, 0), 63);
                float val = xb[(zi * 64 + yi) * 64 + xi];
                acc += v ? val * wgt : 0.f;
            }
        }
    }
    out[idx] = acc;
}

// ---------------- launch ----------------
extern "C" void kernel_launch(void* const* d_in, const int* in_sizes, int n_in,
                              void* d_out, int out_size) {
    const float* x    = (const float*)d_in[0];
    const float* w00  = (const float*)d_in[1];
    const float* b00  = (const float*)d_in[2];
    const float* g00  = (const float*)d_in[3];
    const float* be00 = (const float*)d_in[4];
    const float* w0   = (const float*)d_in[5];
    const float* b0   = (const float*)d_in[6];
    const float* g0   = (const float*)d_in[7];
    const float* be0  = (const float*)d_in[8];
    const float* w1   = (const float*)d_in[9];
    const float* b1   = (const float*)d_in[10];
    const float* g1   = (const float*)d_in[11];
    const float* be1  = (const float*)d_in[12];
    const float* w2   = (const float*)d_in[13];
    const float* b2   = (const float*)d_in[14];
    const float* g2   = (const float*)d_in[15];
    const float* be2  = (const float*)d_in[16];
    const float* w3   = (const float*)d_in[17];
    const float* b3   = (const float*)d_in[18];
    const float* g3   = (const float*)d_in[19];
    const float* be3  = (const float*)d_in[20];
    const float* tw   = (const float*)d_in[21];
    const float* tb   = (const float*)d_in[22];
    const float* rw   = (const float*)d_in[23];
    const float* rb   = (const float*)d_in[24];
    const float* sw   = (const float*)d_in[25];
    const float* sb   = (const float*)d_in[26];
    const float* shw  = (const float*)d_in[27];
    const float* shb  = (const float*)d_in[28];

    float *buf0, *buf1, *buf2, *buf3, *buf4, *scale, *shift, *theta;
    double* stats;
    cudaGetSymbolAddress((void**)&buf0, g_buf0);
    cudaGetSymbolAddress((void**)&buf1, g_buf1);
    cudaGetSymbolAddress((void**)&buf2, g_buf2);
    cudaGetSymbolAddress((void**)&buf3, g_buf3);
    cudaGetSymbolAddress((void**)&buf4, g_buf4);
    cudaGetSymbolAddress((void**)&stats, g_stats);
    cudaGetSymbolAddress((void**)&scale, g_scale);
    cudaGetSymbolAddress((void**)&shift, g_shift);
    cudaGetSymbolAddress((void**)&theta, g_theta);

    // smem v4: (ICC*IZ*IYE*IXP2*2 + COUTB*ICC*27) * 4 = (2*9*9*18*2 + 32*2*27)*4 = 30240
    const int SM_V4 = (2 * 9 * 9 * 18 * 2 + 32 * 2 * 27) * 4;
    const int SM_L3OLD = (16 * 729 + 16 * 16 * 27) * 4;  // 74,304 B (stage 4)
    cudaFuncSetAttribute(conv_s2_v4<16, 32, 8, 4, 4, 2, 2>,
                         cudaFuncAttributeMaxDynamicSharedMemorySize, SM_V4);
    cudaFuncSetAttribute(conv_s2_v4<32, 32, 8, 4, 4, 2, 2>,
                         cudaFuncAttributeMaxDynamicSharedMemorySize, SM_V4);
    cudaFuncSetAttribute(conv_s2_v4<64, 32, 8, 4, 4, 2, 2>,
                         cudaFuncAttributeMaxDynamicSharedMemorySize, SM_V4);
    cudaFuncSetAttribute(conv_s2_kernel<64, 16, 4>,
                         cudaFuncAttributeMaxDynamicSharedMemorySize, SM_L3OLD);

    zero_stats_kernel<<<1, 512>>>(stats);

    // stage 0: conv00 1->16, 64^3 (FFMA2)
    conv00_v2<<<dim3(512, 16), 128>>>(x, w00, b00, buf0, stats + 0);
    finalize_kernel<<<1, 64>>>(stats + 0, g00, be00, scale + 0, shift + 0, 16,
                               1.0 / 4194304.0);

    // stage 1: 16->32, 64^3 -> 32^3; tile (4,4,8): ntx=4, nty=8, ntz=8 -> 256 blocks
    conv_s2_v4<16, 32, 8, 4, 4, 2, 2><<<dim3(256, 16, 1), 128, SM_V4>>>(
        buf0, w0, b0, scale + 0, shift + 0, buf1, stats + 32, 64, 32, 4, 8, 32);
    finalize_kernel<<<1, 64>>>(stats + 32, g0, be0, scale + 64, shift + 64, 32,
                               1.0 / 524288.0);

    // stage 2: 32->64, 32^3 -> 16^3; ntx=2, nty=4, ntz=4 -> 32 blocks; oc 2 z-blocks
    conv_s2_v4<32, 32, 8, 4, 4, 2, 2><<<dim3(32, 16, 2), 128, SM_V4>>>(
        buf1, w1, b1, scale + 64, shift + 64, buf2, stats + 96, 32, 16, 2, 4, 64);
    finalize_kernel<<<1, 64>>>(stats + 96, g1, be1, scale + 128, shift + 128, 64,
                               1.0 / 65536.0);

    // stage 3: 64->64, 16^3 -> 8^3; ntx=1, nty=2, ntz=2 -> 4 blocks; oc 2 z-blocks
    conv_s2_v4<64, 32, 8, 4, 4, 2, 2><<<dim3(4, 16, 2), 128, SM_V4>>>(
        buf2, w2, b2, scale + 128, shift + 128, buf3, stats + 224, 16, 8, 1, 2, 64);
    finalize_kernel<<<1, 64>>>(stats + 224, g2, be2, scale + 192, shift + 192, 64,
                               1.0 / 8192.0);

    // stage 4: 64->64, 8^3 -> 4^3 (tiny; old kernel, oc split into 4 z-blocks)
    conv_s2_kernel<64, 16, 4><<<dim3(1, 16, 4), 128, SM_L3OLD>>>(
        buf3, w3, b3, scale + 192, shift + 192, buf4, stats + 352, 8, 4, 1, 64);
    finalize_kernel<<<1, 64>>>(stats + 352, g3, be3, scale + 256, shift + 256, 64,
                               1.0 / 1024.0);

    // heads + affine composition
    heads_kernel<<<16, 256>>>(buf4, scale + 256, shift + 256, tw, tb, rw, rb, sw, sb,
                              shw, shb, theta);

    // grid sample
    sampler_kernel<<<16384, 256>>>(x, theta, (float*)d_out);
}